// round 12
// baseline (speedup 1.0000x reference)
#include <cuda_runtime.h>
#include <cuda_fp16.h>
#include <cstdint>
#include <math.h>

#define NB   4
#define CC   256
#define HP   66
#define LPIX 4096
#define NPIX 16384

// ======================= PTX helpers ========================================
__device__ __forceinline__ uint32_t smem_u32(const void* p) {
    uint32_t a;
    asm("{ .reg .u64 t; cvta.to.shared.u64 t, %1; cvt.u32.u64 %0, t; }" : "=r"(a) : "l"(p));
    return a;
}
#define CP_ASYNC16(dst, src, sz) \
    asm volatile("cp.async.cg.shared.global [%0], [%1], 16, %2;" \
                 :: "r"(dst), "l"(src), "r"(sz) : "memory")
#define CP_COMMIT() asm volatile("cp.async.commit_group;" ::: "memory")
#define CP_WAIT(n)  asm volatile("cp.async.wait_group %0;" :: "n"(n) : "memory")

#define LDSM4(r0, r1, r2, r3, a) \
    asm volatile("ldmatrix.sync.aligned.m8n8.x4.shared.b16 {%0,%1,%2,%3}, [%4];" \
        : "=r"(r0), "=r"(r1), "=r"(r2), "=r"(r3) : "r"(a))

#define MMA_F16(acc, A, B) \
    asm volatile("mma.sync.aligned.m16n8k16.row.col.f32.f16.f16.f32 " \
        "{%0,%1,%2,%3}, {%4,%5,%6,%7}, {%8,%9}, {%0,%1,%2,%3};" \
        : "+f"((acc)[0]), "+f"((acc)[1]), "+f"((acc)[2]), "+f"((acc)[3]) \
        : "r"((A)[0]), "r"((A)[1]), "r"((A)[2]), "r"((A)[3]), \
          "r"((B)[0]), "r"((B)[1]))

__device__ __forceinline__ void hsplit(float v, __half& h, __half& l) {
    h = __float2half(v);
    l = __float2half(v - __half2float(h));
}

// ======================= scratch ============================================
__device__ float  g_xs [NPIX * CC];
__device__ __half g_xsh[NPIX * CC], g_xsl[NPIX * CC];
__device__ __half g_xp [NB * HP * HP * CC];          // padded x_proj, fp16
__device__ __half g_th [NPIX * CC], g_tl [NPIX * CC];
__device__ float  g_om [NPIX * 216];
__device__ float  g_bom[216];
__device__ __half g_yh [NPIX * CC], g_yl [NPIX * CC];
__device__ float  g_y2 [NPIX * CC];
__device__ float  g_part[NPIX * CC];
__device__ __half g_gh [NPIX * CC];
__device__ float  g_dn [NB * 32 * 32 * CC];
// weights: [N, K] fp16 (hi only)
__device__ __half g_winh[256*256];
__device__ __half g_omh [216*256];
__device__ __half g_wouh[256*256];
__device__ __half g_c1h [256*2304];
__device__ __half g_dnh [256*2304];

// ======================= misc kernels =======================================
__device__ __forceinline__ void block_reduce2(float &a, float &b, float* sh) {
    int lane = threadIdx.x & 31, wid = threadIdx.x >> 5;
#pragma unroll
    for (int o = 16; o; o >>= 1) {
        a += __shfl_down_sync(0xffffffffu, a, o);
        b += __shfl_down_sync(0xffffffffu, b, o);
    }
    if (lane == 0) { sh[wid] = a; sh[8 + wid] = b; }
    __syncthreads();
    if (wid == 0) {
        a = (lane < 8) ? sh[lane] : 0.f;
        b = (lane < 8) ? sh[8 + lane] : 0.f;
#pragma unroll
        for (int o = 4; o; o >>= 1) {
            a += __shfl_down_sync(0xffffffffu, a, o);
            b += __shfl_down_sync(0xffffffffu, b, o);
        }
        if (lane == 0) { sh[16] = a; sh[17] = b; }
    }
    __syncthreads();
    a = sh[16]; b = sh[17];
}

__global__ void k_transpose(const float* __restrict__ x) {
    __shared__ float tile[32][33];
    int n  = blockIdx.z;
    int c0 = blockIdx.x * 32;
    int p0 = blockIdx.y * 32;
    int tx = threadIdx.x, ty = threadIdx.y;
#pragma unroll
    for (int j = 0; j < 32; j += 8)
        tile[ty + j][tx] = x[(size_t)(n * CC + c0 + ty + j) * LPIX + p0 + tx];
    __syncthreads();
#pragma unroll
    for (int j = 0; j < 32; j += 8) {
        float v = tile[tx][ty + j];
        size_t o = (size_t)(n * LPIX + p0 + ty + j) * CC + c0 + tx;
        g_xs[o] = v;
        __half h, l; hsplit(v, h, l);
        g_xsh[o] = h; g_xsl[o] = l;
    }
}

// zero only the 1-pixel border of the padded fp16 buffer (interior overwritten)
__global__ void k_zero_border() {
    int i = blockIdx.x * 256 + threadIdx.x;     // 4 batches * 260 border px * 32 float4
    if (i >= 4 * 260 * 32) return;
    int c4 = i & 31;
    int b  = (i >> 5) % 260;
    int n  = i / (260 * 32);
    int y, x;
    if (b < 66)       { y = 0;       x = b; }
    else if (b < 132) { y = 65;      x = b - 66; }
    else if (b < 196) { y = b - 131; x = 0; }
    else              { y = b - 195; x = 65; }
    reinterpret_cast<float4*>(g_xp + ((size_t)(n * HP + y) * HP + x) * CC)[c4] =
        make_float4(0.f, 0.f, 0.f, 0.f);
}

// tiled transpose weight prep: w [K,N] fp32 -> Wh [N,K] fp16
__global__ void k_wprep(const float* __restrict__ w, __half* __restrict__ Wh, int K, int N) {
    __shared__ float tile[32][33];
    int k0 = blockIdx.x * 32, n0 = blockIdx.y * 32;
    int tx = threadIdx.x, ty = threadIdx.y;   // 32 x 8
#pragma unroll
    for (int j = 0; j < 32; j += 8) {
        int k = k0 + ty + j, n = n0 + tx;
        tile[ty + j][tx] = (k < K && n < N) ? w[(size_t)k * N + n] : 0.f;
    }
    __syncthreads();
#pragma unroll
    for (int j = 0; j < 32; j += 8) {
        int n = n0 + ty + j, k = k0 + tx;
        if (n < N && k < K)
            Wh[(size_t)n * K + k] = __float2half(tile[tx][ty + j]);
    }
}

__global__ void k_bias_cat(const float* __restrict__ b1, const float* __restrict__ b2) {
    int i = threadIdx.x;
    if (i < 144) g_bom[i] = b1[i];
    else if (i < 216) g_bom[i] = b2[i - 144];
}

__global__ void k_dw(const float* __restrict__ dww, const float* __restrict__ dwb,
                     const float* __restrict__ lng, const float* __restrict__ lnb)
{
    int pix = blockIdx.x;
    int c   = threadIdx.x;
    int n = pix >> 12, h = (pix >> 6) & 63, w = pix & 63;
    float acc = dwb[c];
#pragma unroll
    for (int kh = 0; kh < 3; kh++) {
        int y = h + kh - 1;
        if ((unsigned)y >= 64u) continue;
#pragma unroll
        for (int kw = 0; kw < 3; kw++) {
            int x = w + kw - 1;
            if ((unsigned)x >= 64u) continue;
            acc += g_xs[((size_t)((n * 64 + y) * 64 + x)) * 256 + c] *
                   dww[(kh * 3 + kw) * 256 + c];
        }
    }
    __shared__ float sh[32];
    float s = acc, ss = acc * acc;
    block_reduce2(s, ss, sh);
    float mean = s * (1.f / 256.f);
    float var  = ss * (1.f / 256.f) - mean * mean;
    float rstd = rsqrtf(var + 1e-5f);
    float v = (acc - mean) * rstd * lng[c] + lnb[c];
    v = 0.5f * v * (1.f + erff(v * 0.70710678118654752440f));
    __half hh, ll; hsplit(v, hh, ll);
    g_th[(size_t)pix * 256 + c] = hh;
    g_tl[(size_t)pix * 256 + c] = ll;
}

__global__ void k_sample()
{
    int pix  = blockIdx.x;
    int g    = threadIdx.x >> 5;
    int lane = threadIdx.x & 31;
    int n = pix >> 12, h = (pix >> 6) & 63, w = pix & 63;

    const float* ml = g_om + (size_t)pix * 216 + 144 + g * 9;
    float e[9], mx = -1e30f, s = 0.f;
#pragma unroll
    for (int p = 0; p < 9; p++) mx = fmaxf(mx, ml[p]);
#pragma unroll
    for (int p = 0; p < 9; p++) { e[p] = expf(ml[p] - mx); s += e[p]; }
    float inv = 1.f / s;

    const float* off = g_om + (size_t)pix * 216 + g * 18;
    const __half* img = g_xp + (size_t)n * HP * HP * CC + g * 32 + lane;
    float acc = 0.f;
#pragma unroll
    for (int p = 0; p < 9; p++) {
        float px = (float)(w + p / 3) + off[2 * p];
        float py = (float)(h + p % 3) + off[2 * p + 1];
        float wgt = e[p] * inv;
        float x0f = floorf(px), y0f = floorf(py);
        int x0 = (int)x0f, y0 = (int)y0f;
        float fx = px - x0f, fy = py - y0f;
#pragma unroll
        for (int dy = 0; dy < 2; dy++) {
            int yy = y0 + dy;
            if ((unsigned)yy >= (unsigned)HP) continue;
            float wy = dy ? fy : 1.f - fy;
#pragma unroll
            for (int dx = 0; dx < 2; dx++) {
                int xx = x0 + dx;
                if ((unsigned)xx >= (unsigned)HP) continue;
                float wx = dx ? fx : 1.f - fx;
                acc += __half2float(img[((size_t)yy * HP + xx) * CC]) * (wx * wy * wgt);
            }
        }
    }
    __half hh, ll; hsplit(acc, hh, ll);
    g_yh[(size_t)pix * 256 + g * 32 + lane] = hh;
    g_yl[(size_t)pix * 256 + g * 32 + lane] = ll;
}

// GroupNorm(32) [+SiLU]; optional second input summed in; fp32/NCHW and/or fp16 out
__global__ void k_gn(const float* __restrict__ in, const float* __restrict__ in2,
                     float* __restrict__ outf,
                     __half* __restrict__ oh,
                     const float* __restrict__ gamma, const float* __restrict__ beta,
                     int HWn, int do_silu, int out_nchw, int Wd)
{
    int n = blockIdx.x >> 5;
    int g = blockIdx.x & 31;
    int cnt = HWn * 8;
    const float* base  = in  + (size_t)n * HWn * 256 + g * 8;
    const float* base2 = in2 ? in2 + (size_t)n * HWn * 256 + g * 8 : nullptr;
    float s = 0.f, ss = 0.f;
    for (int i = threadIdx.x; i < cnt; i += 256) {
        size_t o = (size_t)(i >> 3) * 256 + (i & 7);
        float v = base[o];
        if (base2) v += base2[o];
        s += v; ss += v * v;
    }
    __shared__ float sh[32];
    block_reduce2(s, ss, sh);
    float mean = s / (float)cnt;
    float rstd = rsqrtf(ss / (float)cnt - mean * mean + 1e-5f);
    for (int i = threadIdx.x; i < cnt; i += 256) {
        int l = i >> 3, c = i & 7;
        size_t o = (size_t)l * 256 + c;
        float v = base[o];
        if (base2) v += base2[o];
        v = (v - mean) * rstd * gamma[g * 8 + c] + beta[g * 8 + c];
        if (do_silu) v = v * (1.f / (1.f + expf(-v)));
        if (outf) {
            if (out_nchw)
                outf[(((size_t)n * 256 + g * 8 + c) * Wd + (l / Wd)) * Wd + (l % Wd)] = v;
            else
                outf[((size_t)n * HWn + l) * 256 + g * 8 + c] = v;
        }
        if (oh)
            oh[((size_t)n * HWn + l) * 256 + g * 8 + c] = __float2half(v);
    }
}

// ======================= mma.sync split-fp16 GEMM ============================
// 512 threads, 16 warps (4M x 4N), warp tile 32x32, CTA tile 128x128, BK=64.
// 2-term (Al!=null): (Ah+Al)*Bh, 4 stages (48KB ea), per-stage barrier
// 1-term (Al==null): Ah*Bh,      6 stages (32KB ea), ONE barrier per 2 stages
// padout: write fp16 into padded 66x66x256 buffer (CoutH)
#define MATB   16384
#define SM_TOT 196608

__global__ void __launch_bounds__(512, 1)
k_mma(const __half* __restrict__ Ah, const __half* __restrict__ Al,
      const __half* __restrict__ Bh,
      const float* __restrict__ bias, float* __restrict__ Cout, float* __restrict__ Cout2,
      __half* __restrict__ CoutH,
      int N, int Kloc, int Kfull, int mode, int owbits, int stride, int padout)
{
    extern __shared__ __align__(128) char smem[];
    const uint32_t sb = smem_u32(smem);
    const int tid = threadIdx.x;
    const int wid = tid >> 5, lane = tid & 31;
    const int g = lane >> 2, tg = lane & 3;
    const int warpM = wid & 3, warpN = wid >> 2;
    const int m0 = blockIdx.x * 128;
    const int n0 = blockIdx.y * 128;
    const int kb = blockIdx.z * Kloc;
    float* Cbase = (blockIdx.z == 0) ? Cout : Cout2;
    const float* bias_eff = (blockIdx.z == 0) ? bias : nullptr;
    const bool twoA  = (Al != nullptr);
    const int nmats  = twoA ? 3 : 2;
    const uint32_t stagesz = (uint32_t)nmats * MATB;
    const int S = Kloc >> 6;

    float acc[2][4][4];
#pragma unroll
    for (int i = 0; i < 2; i++)
#pragma unroll
        for (int j = 0; j < 4; j++)
#pragma unroll
            for (int r = 0; r < 4; r++) acc[i][j][r] = 0.f;

    auto fill = [&](int s, int st) {
        int gk = kb + (s << 6);
        int tap = gk >> 8, ci0 = gk & 255;
        int kh = tap / 3, kw = tap - 3 * kh;
        uint32_t stbase = sb + st * stagesz;
#pragma unroll 3
        for (int q = 0; q < 6; q++) {
            int cid = q * 512 + tid;           // 0..3071
            int mat = cid >> 10;
            if (mat >= nmats) break;
            int idx = cid & 1023;
            int r = idx >> 3, c = idx & 7;
            uint32_t dst = stbase + mat * MATB + r * 128 + ((c ^ (r & 7)) << 4);
            const __half* src;
            int sz = 16;
            if (mat != 1) {                     // A mats
                const __half* Ag = (mat == 0) ? Ah : Al;
                int m = m0 + r;
                if (mode == 0) {
                    src = Ag + (size_t)m * Kfull + gk + c * 8;
                } else {
                    int nn = m >> (2 * owbits);
                    int hw = m & ((1 << (2 * owbits)) - 1);
                    int ohh = hw >> owbits, oww = hw & ((1 << owbits) - 1);
                    int iy = ohh * stride + kh - 1, ix = oww * stride + kw - 1;
                    if ((unsigned)iy < 64u && (unsigned)ix < 64u)
                        src = Ag + ((size_t)((nn * 64 + iy) * 64 + ix)) * 256 + ci0 + c * 8;
                    else { src = Ag; sz = 0; }
                }
            } else {                            // B
                int n = n0 + r;
                if (n < N) src = Bh + (size_t)n * Kfull + gk + c * 8;
                else { src = Bh; sz = 0; }
            }
            CP_ASYNC16(dst, src, sz);
        }
    };

    const int lx = lane & 7;
    const uint32_t laneA_row = (uint32_t)(warpM * 32 + lx + ((lane >> 3) & 1) * 8) * 128;
    const uint32_t laneB_row = (uint32_t)(warpN * 32 + lx + ((lane >> 4) & 1) * 8) * 128;
    const int cselA = (lane >> 4) & 1;
    const int cselB = (lane >> 3) & 1;

    auto compute = [&](int st) {
        uint32_t bAh = sb + st * stagesz;
        uint32_t bBh = bAh + MATB;
        uint32_t bAl = bAh + 2 * MATB;
#pragma unroll
        for (int kk = 0; kk < 4; kk++) {
            uint32_t swzA = (uint32_t)(((kk * 2 + cselA) ^ lx) << 4);
            uint32_t swzB = (uint32_t)(((kk * 2 + cselB) ^ lx) << 4);
            uint32_t ah[2][4], al_[2][4], bh[4][2];
#pragma unroll
            for (int mi = 0; mi < 2; mi++) {
                LDSM4(ah[mi][0], ah[mi][1], ah[mi][2], ah[mi][3],
                      bAh + laneA_row + mi * 2048 + swzA);
                if (twoA)
                    LDSM4(al_[mi][0], al_[mi][1], al_[mi][2], al_[mi][3],
                          bAl + laneA_row + mi * 2048 + swzA);
            }
#pragma unroll
            for (int np = 0; np < 2; np++)
                LDSM4(bh[np*2][0], bh[np*2][1], bh[np*2+1][0], bh[np*2+1][1],
                      bBh + laneB_row + np * 2048 + swzB);
#pragma unroll
            for (int mi = 0; mi < 2; mi++)
#pragma unroll
                for (int ni = 0; ni < 4; ni++)
                    MMA_F16(acc[mi][ni], ah[mi], bh[ni]);
            if (twoA) {
#pragma unroll
                for (int mi = 0; mi < 2; mi++)
#pragma unroll
                    for (int ni = 0; ni < 4; ni++)
                        MMA_F16(acc[mi][ni], al_[mi], bh[ni]);
            }
        }
    };

    if (twoA) {
        // depth 4, per-stage barrier
        for (int s = 0; s < 3; s++) { if (s < S) fill(s, s); CP_COMMIT(); }
        int st = 0;
        for (int s = 0; s < S; s++) {
            CP_WAIT(2);
            __syncthreads();
            int stf = st + 3; if (stf >= 4) stf -= 4;
            if (s + 3 < S) fill(s + 3, stf);
            CP_COMMIT();
            compute(st);
            if (++st == 4) st = 0;
        }
    } else {
        // depth 6, one barrier per 2 stages (S is even for the convs)
        for (int s = 0; s < 4; s++) { if (s < S) fill(s, s); CP_COMMIT(); }
        int st = 0;
        for (int s = 0; s < S; s += 2) {
            CP_WAIT(2);
            __syncthreads();
            int f0 = st + 4; if (f0 >= 6) f0 -= 6;
            int f1 = st + 5; if (f1 >= 6) f1 -= 6;
            if (s + 4 < S) fill(s + 4, f0);
            CP_COMMIT();
            if (s + 5 < S) fill(s + 5, f1);
            CP_COMMIT();
            compute(st);
            int st1 = st + 1; if (st1 >= 6) st1 -= 6;
            compute(st1);
            st += 2; if (st >= 6) st -= 6;
        }
    }

    // ---- epilogue ----
#pragma unroll
    for (int mi = 0; mi < 2; mi++) {
        int mA = m0 + warpM * 32 + mi * 16 + g;
#pragma unroll
        for (int half = 0; half < 2; half++) {
            int m = mA + half * 8;
            if (padout) {
                int n = m >> 12, h = (m >> 6) & 63, w = m & 63;
                __half* orow = CoutH + ((size_t)(n * HP + h + 1) * HP + (w + 1)) * 256;
#pragma unroll
                for (int ni = 0; ni < 4; ni++) {
                    int nc = n0 + warpN * 32 + ni * 8 + tg * 2;
                    float v0 = acc[mi][ni][half * 2]     + bias[nc];
                    float v1 = acc[mi][ni][half * 2 + 1] + bias[nc + 1];
                    *reinterpret_cast<__half2*>(orow + nc) = __floats2half2_rn(v0, v1);
                }
            } else {
                float* orow = Cbase + (size_t)m * N;
#pragma unroll
                for (int ni = 0; ni < 4; ni++) {
                    int nc = n0 + warpN * 32 + ni * 8 + tg * 2;
                    float b0 = bias_eff ? bias_eff[nc < N ? nc : 0] : 0.f;
                    float b1 = bias_eff ? bias_eff[nc + 1 < N ? nc + 1 : 0] : 0.f;
                    if (nc < N)     orow[nc]     = acc[mi][ni][half * 2]     + b0;
                    if (nc + 1 < N) orow[nc + 1] = acc[mi][ni][half * 2 + 1] + b1;
                }
            }
        }
    }
}

// ======================= launch =============================================
extern "C" void kernel_launch(void* const* d_in, const int* in_sizes, int n_in,
                              void* d_out, int out_size)
{
    const float* x      = (const float*)d_in[0];
    const float* w_in   = (const float*)d_in[1];
    const float* b_in   = (const float*)d_in[2];
    const float* dw_w   = (const float*)d_in[3];
    const float* dw_b   = (const float*)d_in[4];
    const float* ln_g   = (const float*)d_in[5];
    const float* ln_b   = (const float*)d_in[6];
    const float* w_off  = (const float*)d_in[7];
    const float* b_off  = (const float*)d_in[8];
    const float* w_mask = (const float*)d_in[9];
    const float* b_mask = (const float*)d_in[10];
    const float* w_out  = (const float*)d_in[11];
    const float* b_out  = (const float*)d_in[12];
    const float* gn1_g  = (const float*)d_in[13];
    const float* gn1_b  = (const float*)d_in[14];
    const float* c1_w   = (const float*)d_in[15];
    const float* c1_b   = (const float*)d_in[16];
    const float* gn2_g  = (const float*)d_in[17];
    const float* gn2_b  = (const float*)d_in[18];
    const float* dn_w   = (const float*)d_in[19];
    const float* dn_b   = (const float*)d_in[20];
    const float* gn3_g  = (const float*)d_in[21];
    const float* gn3_b  = (const float*)d_in[22];

    cudaFuncSetAttribute(k_mma, cudaFuncAttributeMaxDynamicSharedMemorySize, SM_TOT);

    float *om, *bom, *y2, *part, *dn;
    __half *xp, *xsh, *xsl, *th, *tl, *yh, *yl, *gh;
    __half *winh, *omh, *wouh, *c1h, *dnh;
    cudaGetSymbolAddress((void**)&xp,  g_xp);
    cudaGetSymbolAddress((void**)&om,  g_om);
    cudaGetSymbolAddress((void**)&bom, g_bom);
    cudaGetSymbolAddress((void**)&y2,  g_y2);
    cudaGetSymbolAddress((void**)&part, g_part);
    cudaGetSymbolAddress((void**)&dn,  g_dn);
    cudaGetSymbolAddress((void**)&xsh, g_xsh); cudaGetSymbolAddress((void**)&xsl, g_xsl);
    cudaGetSymbolAddress((void**)&th,  g_th);  cudaGetSymbolAddress((void**)&tl,  g_tl);
    cudaGetSymbolAddress((void**)&yh,  g_yh);  cudaGetSymbolAddress((void**)&yl,  g_yl);
    cudaGetSymbolAddress((void**)&gh,  g_gh);
    cudaGetSymbolAddress((void**)&winh, g_winh);
    cudaGetSymbolAddress((void**)&omh,  g_omh);
    cudaGetSymbolAddress((void**)&wouh, g_wouh);
    cudaGetSymbolAddress((void**)&c1h,  g_c1h);  cudaGetSymbolAddress((void**)&dnh,  g_dnh);

    dim3 wblk(32, 8);
    k_transpose<<<dim3(8, 128, 4), wblk>>>(x);                                   // 0
    k_zero_border<<<130, 256>>>();                                               // 1
    k_wprep<<<dim3(8, 8), wblk>>>(w_in, winh, 256, 256);                         // 2
    // 3: input projection -> padded xp fp16 (2-term)   [PROFILED LAUNCH]
    k_mma<<<dim3(128, 2, 1), 512, SM_TOT>>>(xsh, xsl, winh, b_in, nullptr, nullptr, xp,
                                            256, 256, 256, 0, 0, 0, 1);
    // remaining weight preps
    k_wprep<<<dim3(8, 5), wblk>>>(w_off,  omh,             256, 144);
    k_wprep<<<dim3(8, 3), wblk>>>(w_mask, omh + 144 * 256, 256, 72);
    k_bias_cat<<<1, 256>>>(b_off, b_mask);
    k_wprep<<<dim3(8, 8),  wblk>>>(w_out, wouh, 256, 256);
    k_wprep<<<dim3(72, 8), wblk>>>(c1_w, c1h, 2304, 256);
    k_wprep<<<dim3(72, 8), wblk>>>(dn_w, dnh, 2304, 256);
    // depthwise + LN + GELU -> t (fp16 split)
    k_dw<<<NPIX, 256>>>(dw_w, dw_b, ln_g, ln_b);
    // fused offset+mask projection (N=216, 2-term)
    k_mma<<<dim3(128, 2, 1), 512, SM_TOT>>>(th, tl, omh, bom, om, nullptr, nullptr,
                                            216, 256, 256, 0, 0, 0, 0);
    // deformable sampling -> y (fp16 split)
    k_sample<<<NPIX, 256>>>();
    // output projection -> y2 (2-term)
    k_mma<<<dim3(128, 2, 1), 512, SM_TOT>>>(yh, yl, wouh, b_out, y2, nullptr, nullptr,
                                            256, 256, 256, 0, 0, 0, 0);
    // GN1 + SiLU -> fp16 (hi only)
    k_gn<<<128, 256>>>(y2, nullptr, (float*)nullptr, gh, gn1_g, gn1_b, 4096, 1, 0, 64);
    // conv1 3x3 implicit im2col (K=2304, 1-term fp16, K-split z=2) -> y2 + part
    k_mma<<<dim3(128, 2, 2), 512, SM_TOT>>>(gh, nullptr, c1h, c1_b, y2, part, nullptr,
                                            256, 1152, 2304, 1, 6, 1, 0);
    // GN2 (sums y2 + part) + SiLU -> fp16 (hi only)
    k_gn<<<128, 256>>>(y2, part, (float*)nullptr, gh, gn2_g, gn2_b, 4096, 1, 0, 64);
    // down conv 3x3 stride2 (1-term, K-split z=2: dn + partial in y2)
    k_mma<<<dim3(32, 2, 2), 512, SM_TOT>>>(gh, nullptr, dnh, dn_b, dn, y2, nullptr,
                                           256, 1152, 2304, 1, 5, 2, 0);
    // GN3 (sums dn + y2 partial) -> NCHW output
    k_gn<<<128, 256>>>(dn, y2, (float*)d_out, (__half*)nullptr,
                       gn3_g, gn3_b, 1024, 0, 1, 32);
}

// round 13
// speedup vs baseline: 1.0587x; 1.0587x over previous
#include <cuda_runtime.h>
#include <cuda_fp16.h>
#include <cstdint>
#include <math.h>

#define NB   4
#define CC   256
#define HP   66
#define LPIX 4096
#define NPIX 16384

// ======================= PTX helpers ========================================
__device__ __forceinline__ uint32_t smem_u32(const void* p) {
    uint32_t a;
    asm("{ .reg .u64 t; cvta.to.shared.u64 t, %1; cvt.u32.u64 %0, t; }" : "=r"(a) : "l"(p));
    return a;
}
#define CP_ASYNC16(dst, src, sz) \
    asm volatile("cp.async.cg.shared.global [%0], [%1], 16, %2;" \
                 :: "r"(dst), "l"(src), "r"(sz) : "memory")
#define CP_COMMIT() asm volatile("cp.async.commit_group;" ::: "memory")
#define CP_WAIT(n)  asm volatile("cp.async.wait_group %0;" :: "n"(n) : "memory")

#define LDSM4(r0, r1, r2, r3, a) \
    asm volatile("ldmatrix.sync.aligned.m8n8.x4.shared.b16 {%0,%1,%2,%3}, [%4];" \
        : "=r"(r0), "=r"(r1), "=r"(r2), "=r"(r3) : "r"(a))

#define MMA_F16(acc, A, B) \
    asm volatile("mma.sync.aligned.m16n8k16.row.col.f32.f16.f16.f32 " \
        "{%0,%1,%2,%3}, {%4,%5,%6,%7}, {%8,%9}, {%0,%1,%2,%3};" \
        : "+f"((acc)[0]), "+f"((acc)[1]), "+f"((acc)[2]), "+f"((acc)[3]) \
        : "r"((A)[0]), "r"((A)[1]), "r"((A)[2]), "r"((A)[3]), \
          "r"((B)[0]), "r"((B)[1]))

__device__ __forceinline__ void hsplit(float v, __half& h, __half& l) {
    h = __float2half(v);
    l = __float2half(v - __half2float(h));
}

// ======================= scratch ============================================
__device__ float  g_xs [NPIX * CC];
__device__ __half g_xsh[NPIX * CC];
__device__ __half g_xp [NB * HP * HP * CC];          // padded x_proj, fp16
__device__ __half g_th [NPIX * CC], g_tl [NPIX * CC];
__device__ float  g_om [NPIX * 216];
__device__ float  g_bom[216];
__device__ __half g_yh [NPIX * CC];
__device__ float  g_y2 [NPIX * CC];
__device__ __half g_gh [NPIX * CC];
__device__ float  g_dn [NB * 32 * 32 * CC];
// weights: [N, K] fp16 (hi only)
__device__ __half g_winh[256*256];
__device__ __half g_omh [216*256];
__device__ __half g_wouh[256*256];
__device__ __half g_c1h [256*2304];
__device__ __half g_dnh [256*2304];

// ======================= misc kernels =======================================
__device__ __forceinline__ void block_reduce2(float &a, float &b, float* sh) {
    int lane = threadIdx.x & 31, wid = threadIdx.x >> 5;
#pragma unroll
    for (int o = 16; o; o >>= 1) {
        a += __shfl_down_sync(0xffffffffu, a, o);
        b += __shfl_down_sync(0xffffffffu, b, o);
    }
    if (lane == 0) { sh[wid] = a; sh[8 + wid] = b; }
    __syncthreads();
    if (wid == 0) {
        a = (lane < 8) ? sh[lane] : 0.f;
        b = (lane < 8) ? sh[8 + lane] : 0.f;
#pragma unroll
        for (int o = 4; o; o >>= 1) {
            a += __shfl_down_sync(0xffffffffu, a, o);
            b += __shfl_down_sync(0xffffffffu, b, o);
        }
        if (lane == 0) { sh[16] = a; sh[17] = b; }
    }
    __syncthreads();
    a = sh[16]; b = sh[17];
}

__global__ void k_transpose(const float* __restrict__ x) {
    __shared__ float tile[32][33];
    int n  = blockIdx.z;
    int c0 = blockIdx.x * 32;
    int p0 = blockIdx.y * 32;
    int tx = threadIdx.x, ty = threadIdx.y;
#pragma unroll
    for (int j = 0; j < 32; j += 8)
        tile[ty + j][tx] = x[(size_t)(n * CC + c0 + ty + j) * LPIX + p0 + tx];
    __syncthreads();
#pragma unroll
    for (int j = 0; j < 32; j += 8) {
        float v = tile[tx][ty + j];
        size_t o = (size_t)(n * LPIX + p0 + ty + j) * CC + c0 + tx;
        g_xs[o] = v;
        g_xsh[o] = __float2half(v);
    }
}

// zero only the 1-pixel border of the padded fp16 buffer (interior overwritten)
__global__ void k_zero_border() {
    int i = blockIdx.x * 256 + threadIdx.x;     // 4 batches * 260 border px * 32 float4
    if (i >= 4 * 260 * 32) return;
    int c4 = i & 31;
    int b  = (i >> 5) % 260;
    int n  = i / (260 * 32);
    int y, x;
    if (b < 66)       { y = 0;       x = b; }
    else if (b < 132) { y = 65;      x = b - 66; }
    else if (b < 196) { y = b - 131; x = 0; }
    else              { y = b - 195; x = 65; }
    reinterpret_cast<float4*>(g_xp + ((size_t)(n * HP + y) * HP + x) * CC)[c4] =
        make_float4(0.f, 0.f, 0.f, 0.f);
}

// tiled transpose weight prep: w [K,N] fp32 -> Wh [N,K] fp16
__global__ void k_wprep(const float* __restrict__ w, __half* __restrict__ Wh, int K, int N) {
    __shared__ float tile[32][33];
    int k0 = blockIdx.x * 32, n0 = blockIdx.y * 32;
    int tx = threadIdx.x, ty = threadIdx.y;   // 32 x 8
#pragma unroll
    for (int j = 0; j < 32; j += 8) {
        int k = k0 + ty + j, n = n0 + tx;
        tile[ty + j][tx] = (k < K && n < N) ? w[(size_t)k * N + n] : 0.f;
    }
    __syncthreads();
#pragma unroll
    for (int j = 0; j < 32; j += 8) {
        int n = n0 + ty + j, k = k0 + tx;
        if (n < N && k < K)
            Wh[(size_t)n * K + k] = __float2half(tile[tx][ty + j]);
    }
}

__global__ void k_bias_cat(const float* __restrict__ b1, const float* __restrict__ b2) {
    int i = threadIdx.x;
    if (i < 144) g_bom[i] = b1[i];
    else if (i < 216) g_bom[i] = b2[i - 144];
}

__global__ void k_dw(const float* __restrict__ dww, const float* __restrict__ dwb,
                     const float* __restrict__ lng, const float* __restrict__ lnb)
{
    int pix = blockIdx.x;
    int c   = threadIdx.x;
    int n = pix >> 12, h = (pix >> 6) & 63, w = pix & 63;
    float acc = dwb[c];
#pragma unroll
    for (int kh = 0; kh < 3; kh++) {
        int y = h + kh - 1;
        if ((unsigned)y >= 64u) continue;
#pragma unroll
        for (int kw = 0; kw < 3; kw++) {
            int x = w + kw - 1;
            if ((unsigned)x >= 64u) continue;
            acc += g_xs[((size_t)((n * 64 + y) * 64 + x)) * 256 + c] *
                   dww[(kh * 3 + kw) * 256 + c];
        }
    }
    __shared__ float sh[32];
    float s = acc, ss = acc * acc;
    block_reduce2(s, ss, sh);
    float mean = s * (1.f / 256.f);
    float var  = ss * (1.f / 256.f) - mean * mean;
    float rstd = rsqrtf(var + 1e-5f);
    float v = (acc - mean) * rstd * lng[c] + lnb[c];
    v = 0.5f * v * (1.f + erff(v * 0.70710678118654752440f));
    __half hh, ll; hsplit(v, hh, ll);
    g_th[(size_t)pix * 256 + c] = hh;
    g_tl[(size_t)pix * 256 + c] = ll;
}

__global__ void k_sample()
{
    int pix  = blockIdx.x;
    int g    = threadIdx.x >> 5;
    int lane = threadIdx.x & 31;
    int n = pix >> 12, h = (pix >> 6) & 63, w = pix & 63;

    const float* ml = g_om + (size_t)pix * 216 + 144 + g * 9;
    float e[9], mx = -1e30f, s = 0.f;
#pragma unroll
    for (int p = 0; p < 9; p++) mx = fmaxf(mx, ml[p]);
#pragma unroll
    for (int p = 0; p < 9; p++) { e[p] = expf(ml[p] - mx); s += e[p]; }
    float inv = 1.f / s;

    const float* off = g_om + (size_t)pix * 216 + g * 18;
    const __half* img = g_xp + (size_t)n * HP * HP * CC + g * 32 + lane;
    float acc = 0.f;
#pragma unroll
    for (int p = 0; p < 9; p++) {
        float px = (float)(w + p / 3) + off[2 * p];
        float py = (float)(h + p % 3) + off[2 * p + 1];
        float wgt = e[p] * inv;
        float x0f = floorf(px), y0f = floorf(py);
        int x0 = (int)x0f, y0 = (int)y0f;
        float fx = px - x0f, fy = py - y0f;
#pragma unroll
        for (int dy = 0; dy < 2; dy++) {
            int yy = y0 + dy;
            if ((unsigned)yy >= (unsigned)HP) continue;
            float wy = dy ? fy : 1.f - fy;
#pragma unroll
            for (int dx = 0; dx < 2; dx++) {
                int xx = x0 + dx;
                if ((unsigned)xx >= (unsigned)HP) continue;
                float wx = dx ? fx : 1.f - fx;
                acc += __half2float(img[((size_t)yy * HP + xx) * CC]) * (wx * wy * wgt);
            }
        }
    }
    g_yh[(size_t)pix * 256 + g * 32 + lane] = __float2half(acc);
}

// GroupNorm(32) [+SiLU]; optional second input summed in; fp32/NCHW and/or fp16 out
__global__ void k_gn(const float* __restrict__ in, const float* __restrict__ in2,
                     float* __restrict__ outf,
                     __half* __restrict__ oh,
                     const float* __restrict__ gamma, const float* __restrict__ beta,
                     int HWn, int do_silu, int out_nchw, int Wd)
{
    int n = blockIdx.x >> 5;
    int g = blockIdx.x & 31;
    int cnt = HWn * 8;
    const float* base  = in  + (size_t)n * HWn * 256 + g * 8;
    const float* base2 = in2 ? in2 + (size_t)n * HWn * 256 + g * 8 : nullptr;
    float s = 0.f, ss = 0.f;
    for (int i = threadIdx.x; i < cnt; i += 256) {
        size_t o = (size_t)(i >> 3) * 256 + (i & 7);
        float v = base[o];
        if (base2) v += base2[o];
        s += v; ss += v * v;
    }
    __shared__ float sh[32];
    block_reduce2(s, ss, sh);
    float mean = s / (float)cnt;
    float rstd = rsqrtf(ss / (float)cnt - mean * mean + 1e-5f);
    for (int i = threadIdx.x; i < cnt; i += 256) {
        int l = i >> 3, c = i & 7;
        size_t o = (size_t)l * 256 + c;
        float v = base[o];
        if (base2) v += base2[o];
        v = (v - mean) * rstd * gamma[g * 8 + c] + beta[g * 8 + c];
        if (do_silu) v = v * (1.f / (1.f + expf(-v)));
        if (outf) {
            if (out_nchw)
                outf[(((size_t)n * 256 + g * 8 + c) * Wd + (l / Wd)) * Wd + (l % Wd)] = v;
            else
                outf[((size_t)n * HWn + l) * 256 + g * 8 + c] = v;
        }
        if (oh)
            oh[((size_t)n * HWn + l) * 256 + g * 8 + c] = __float2half(v);
    }
}

// ======================= mma.sync split-fp16 GEMM ============================
// 512 threads, 16 warps (4M x 4N), warp tile 32x32, CTA tile 128x128, BK=64.
// 2-term (Al!=null): (Ah+Al)*Bh, 4 stages (48KB ea), per-stage barrier
// 1-term (Al==null): Ah*Bh,      6 stages (32KB ea), ONE barrier per 2 stages
// padout: write fp16 into padded 66x66x256 buffer (CoutH)
#define MATB   16384
#define SM_TOT 196608

__global__ void __launch_bounds__(512, 1)
k_mma(const __half* __restrict__ Ah, const __half* __restrict__ Al,
      const __half* __restrict__ Bh,
      const float* __restrict__ bias, float* __restrict__ Cout, float* __restrict__ Cout2,
      __half* __restrict__ CoutH,
      int N, int Kloc, int Kfull, int mode, int owbits, int stride, int padout)
{
    extern __shared__ __align__(128) char smem[];
    const uint32_t sb = smem_u32(smem);
    const int tid = threadIdx.x;
    const int wid = tid >> 5, lane = tid & 31;
    const int g = lane >> 2, tg = lane & 3;
    const int warpM = wid & 3, warpN = wid >> 2;
    const int m0 = blockIdx.x * 128;
    const int n0 = blockIdx.y * 128;
    const int kb = blockIdx.z * Kloc;
    float* Cbase = (blockIdx.z == 0) ? Cout : Cout2;
    const float* bias_eff = (blockIdx.z == 0) ? bias : nullptr;
    const bool twoA  = (Al != nullptr);
    const int nmats  = twoA ? 3 : 2;
    const uint32_t stagesz = (uint32_t)nmats * MATB;
    const int S = Kloc >> 6;

    float acc[2][4][4];
#pragma unroll
    for (int i = 0; i < 2; i++)
#pragma unroll
        for (int j = 0; j < 4; j++)
#pragma unroll
            for (int r = 0; r < 4; r++) acc[i][j][r] = 0.f;

    auto fill = [&](int s, int st) {
        int gk = kb + (s << 6);
        int tap = gk >> 8, ci0 = gk & 255;
        int kh = tap / 3, kw = tap - 3 * kh;
        uint32_t stbase = sb + st * stagesz;
#pragma unroll 3
        for (int q = 0; q < 6; q++) {
            int cid = q * 512 + tid;           // 0..3071
            int mat = cid >> 10;
            if (mat >= nmats) break;
            int idx = cid & 1023;
            int r = idx >> 3, c = idx & 7;
            uint32_t dst = stbase + mat * MATB + r * 128 + ((c ^ (r & 7)) << 4);
            const __half* src;
            int sz = 16;
            if (mat != 1) {                     // A mats
                const __half* Ag = (mat == 0) ? Ah : Al;
                int m = m0 + r;
                if (mode == 0) {
                    src = Ag + (size_t)m * Kfull + gk + c * 8;
                } else {
                    int nn = m >> (2 * owbits);
                    int hw = m & ((1 << (2 * owbits)) - 1);
                    int ohh = hw >> owbits, oww = hw & ((1 << owbits) - 1);
                    int iy = ohh * stride + kh - 1, ix = oww * stride + kw - 1;
                    if ((unsigned)iy < 64u && (unsigned)ix < 64u)
                        src = Ag + ((size_t)((nn * 64 + iy) * 64 + ix)) * 256 + ci0 + c * 8;
                    else { src = Ag; sz = 0; }
                }
            } else {                            // B
                int n = n0 + r;
                if (n < N) src = Bh + (size_t)n * Kfull + gk + c * 8;
                else { src = Bh; sz = 0; }
            }
            CP_ASYNC16(dst, src, sz);
        }
    };

    const int lx = lane & 7;
    const uint32_t laneA_row = (uint32_t)(warpM * 32 + lx + ((lane >> 3) & 1) * 8) * 128;
    const uint32_t laneB_row = (uint32_t)(warpN * 32 + lx + ((lane >> 4) & 1) * 8) * 128;
    const int cselA = (lane >> 4) & 1;
    const int cselB = (lane >> 3) & 1;

    auto compute = [&](int st) {
        uint32_t bAh = sb + st * stagesz;
        uint32_t bBh = bAh + MATB;
        uint32_t bAl = bAh + 2 * MATB;
#pragma unroll
        for (int kk = 0; kk < 4; kk++) {
            uint32_t swzA = (uint32_t)(((kk * 2 + cselA) ^ lx) << 4);
            uint32_t swzB = (uint32_t)(((kk * 2 + cselB) ^ lx) << 4);
            uint32_t ah[2][4], al_[2][4], bh[4][2];
#pragma unroll
            for (int mi = 0; mi < 2; mi++) {
                LDSM4(ah[mi][0], ah[mi][1], ah[mi][2], ah[mi][3],
                      bAh + laneA_row + mi * 2048 + swzA);
                if (twoA)
                    LDSM4(al_[mi][0], al_[mi][1], al_[mi][2], al_[mi][3],
                          bAl + laneA_row + mi * 2048 + swzA);
            }
#pragma unroll
            for (int np = 0; np < 2; np++)
                LDSM4(bh[np*2][0], bh[np*2][1], bh[np*2+1][0], bh[np*2+1][1],
                      bBh + laneB_row + np * 2048 + swzB);
#pragma unroll
            for (int mi = 0; mi < 2; mi++)
#pragma unroll
                for (int ni = 0; ni < 4; ni++)
                    MMA_F16(acc[mi][ni], ah[mi], bh[ni]);
            if (twoA) {
#pragma unroll
                for (int mi = 0; mi < 2; mi++)
#pragma unroll
                    for (int ni = 0; ni < 4; ni++)
                        MMA_F16(acc[mi][ni], al_[mi], bh[ni]);
            }
        }
    };

    if (twoA) {
        // depth 4, per-stage barrier
        for (int s = 0; s < 3; s++) { if (s < S) fill(s, s); CP_COMMIT(); }
        int st = 0;
        for (int s = 0; s < S; s++) {
            CP_WAIT(2);
            __syncthreads();
            int stf = st + 3; if (stf >= 4) stf -= 4;
            if (s + 3 < S) fill(s + 3, stf);
            CP_COMMIT();
            compute(st);
            if (++st == 4) st = 0;
        }
    } else {
        // depth 6, one barrier per 2 stages (S is even for all 1-term calls)
        for (int s = 0; s < 4; s++) { if (s < S) fill(s, s); CP_COMMIT(); }
        int st = 0;
        for (int s = 0; s < S; s += 2) {
            CP_WAIT(2);
            __syncthreads();
            int f0 = st + 4; if (f0 >= 6) f0 -= 6;
            int f1 = st + 5; if (f1 >= 6) f1 -= 6;
            if (s + 4 < S) fill(s + 4, f0);
            CP_COMMIT();
            if (s + 5 < S) fill(s + 5, f1);
            CP_COMMIT();
            compute(st);
            int st1 = st + 1; if (st1 >= 6) st1 -= 6;
            compute(st1);
            st += 2; if (st >= 6) st -= 6;
        }
    }

    // ---- epilogue ----
#pragma unroll
    for (int mi = 0; mi < 2; mi++) {
        int mA = m0 + warpM * 32 + mi * 16 + g;
#pragma unroll
        for (int half = 0; half < 2; half++) {
            int m = mA + half * 8;
            if (padout) {
                int n = m >> 12, h = (m >> 6) & 63, w = m & 63;
                __half* orow = CoutH + ((size_t)(n * HP + h + 1) * HP + (w + 1)) * 256;
#pragma unroll
                for (int ni = 0; ni < 4; ni++) {
                    int nc = n0 + warpN * 32 + ni * 8 + tg * 2;
                    float v0 = acc[mi][ni][half * 2]     + bias[nc];
                    float v1 = acc[mi][ni][half * 2 + 1] + bias[nc + 1];
                    *reinterpret_cast<__half2*>(orow + nc) = __floats2half2_rn(v0, v1);
                }
            } else {
                float* orow = Cbase + (size_t)m * N;
#pragma unroll
                for (int ni = 0; ni < 4; ni++) {
                    int nc = n0 + warpN * 32 + ni * 8 + tg * 2;
                    float b0 = bias_eff ? bias_eff[nc < N ? nc : 0] : 0.f;
                    float b1 = bias_eff ? bias_eff[nc + 1 < N ? nc + 1 : 0] : 0.f;
                    if (nc < N)     orow[nc]     = acc[mi][ni][half * 2]     + b0;
                    if (nc + 1 < N) orow[nc + 1] = acc[mi][ni][half * 2 + 1] + b1;
                }
            }
        }
    }
}

// ======================= launch =============================================
extern "C" void kernel_launch(void* const* d_in, const int* in_sizes, int n_in,
                              void* d_out, int out_size)
{
    const float* x      = (const float*)d_in[0];
    const float* w_in   = (const float*)d_in[1];
    const float* b_in   = (const float*)d_in[2];
    const float* dw_w   = (const float*)d_in[3];
    const float* dw_b   = (const float*)d_in[4];
    const float* ln_g   = (const float*)d_in[5];
    const float* ln_b   = (const float*)d_in[6];
    const float* w_off  = (const float*)d_in[7];
    const float* b_off  = (const float*)d_in[8];
    const float* w_mask = (const float*)d_in[9];
    const float* b_mask = (const float*)d_in[10];
    const float* w_out  = (const float*)d_in[11];
    const float* b_out  = (const float*)d_in[12];
    const float* gn1_g  = (const float*)d_in[13];
    const float* gn1_b  = (const float*)d_in[14];
    const float* c1_w   = (const float*)d_in[15];
    const float* c1_b   = (const float*)d_in[16];
    const float* gn2_g  = (const float*)d_in[17];
    const float* gn2_b  = (const float*)d_in[18];
    const float* dn_w   = (const float*)d_in[19];
    const float* dn_b   = (const float*)d_in[20];
    const float* gn3_g  = (const float*)d_in[21];
    const float* gn3_b  = (const float*)d_in[22];

    cudaFuncSetAttribute(k_mma, cudaFuncAttributeMaxDynamicSharedMemorySize, SM_TOT);

    float *om, *bom, *y2, *dn;
    __half *xp, *xsh, *th, *tl, *yh, *gh;
    __half *winh, *omh, *wouh, *c1h, *dnh;
    cudaGetSymbolAddress((void**)&xp,  g_xp);
    cudaGetSymbolAddress((void**)&om,  g_om);
    cudaGetSymbolAddress((void**)&bom, g_bom);
    cudaGetSymbolAddress((void**)&y2,  g_y2);
    cudaGetSymbolAddress((void**)&dn,  g_dn);
    cudaGetSymbolAddress((void**)&xsh, g_xsh);
    cudaGetSymbolAddress((void**)&th,  g_th);  cudaGetSymbolAddress((void**)&tl,  g_tl);
    cudaGetSymbolAddress((void**)&yh,  g_yh);
    cudaGetSymbolAddress((void**)&gh,  g_gh);
    cudaGetSymbolAddress((void**)&winh, g_winh);
    cudaGetSymbolAddress((void**)&omh,  g_omh);
    cudaGetSymbolAddress((void**)&wouh, g_wouh);
    cudaGetSymbolAddress((void**)&c1h,  g_c1h);  cudaGetSymbolAddress((void**)&dnh,  g_dnh);

    dim3 wblk(32, 8);
    k_transpose<<<dim3(8, 128, 4), wblk>>>(x);                                   // 0
    k_zero_border<<<130, 256>>>();                                               // 1
    k_wprep<<<dim3(8, 8), wblk>>>(w_in, winh, 256, 256);                         // 2
    // 3: input projection -> padded xp fp16 (1-term)   [PROFILED LAUNCH]
    k_mma<<<dim3(128, 2, 1), 512, SM_TOT>>>(xsh, nullptr, winh, b_in, nullptr, nullptr, xp,
                                            256, 256, 256, 0, 0, 0, 1);
    // remaining weight preps
    k_wprep<<<dim3(8, 5), wblk>>>(w_off,  omh,             256, 144);
    k_wprep<<<dim3(8, 3), wblk>>>(w_mask, omh + 144 * 256, 256, 72);
    k_bias_cat<<<1, 256>>>(b_off, b_mask);
    k_wprep<<<dim3(8, 8),  wblk>>>(w_out, wouh, 256, 256);
    k_wprep<<<dim3(72, 8), wblk>>>(c1_w, c1h, 2304, 256);
    k_wprep<<<dim3(72, 8), wblk>>>(dn_w, dnh, 2304, 256);
    // depthwise + LN + GELU -> t (fp16 split)
    k_dw<<<NPIX, 256>>>(dw_w, dw_b, ln_g, ln_b);
    // fused offset+mask projection (N=216, 2-term: exact-A anchors positions)
    k_mma<<<dim3(128, 2, 1), 512, SM_TOT>>>(th, tl, omh, bom, om, nullptr, nullptr,
                                            216, 256, 256, 0, 0, 0, 0);
    // deformable sampling -> y (fp16)
    k_sample<<<NPIX, 256>>>();
    // output projection -> y2 (1-term)
    k_mma<<<dim3(128, 2, 1), 512, SM_TOT>>>(yh, nullptr, wouh, b_out, y2, nullptr, nullptr,
                                            256, 256, 256, 0, 0, 0, 0);
    // GN1 + SiLU -> fp16 (hi only)
    k_gn<<<128, 256>>>(y2, nullptr, (float*)nullptr, gh, gn1_g, gn1_b, 4096, 1, 0, 64);
    // conv1 3x3 implicit im2col (K=2304, 1-term fp16, paired stages) -> y2
    k_mma<<<dim3(128, 2, 1), 512, SM_TOT>>>(gh, nullptr, c1h, c1_b, y2, nullptr, nullptr,
                                            256, 2304, 2304, 1, 6, 1, 0);
    // GN2 + SiLU -> fp16 (hi only)
    k_gn<<<128, 256>>>(y2, nullptr, (float*)nullptr, gh, gn2_g, gn2_b, 4096, 1, 0, 64);
    // down conv 3x3 stride2 (1-term, K-split z=2: dn + partial in y2)
    k_mma<<<dim3(32, 2, 2), 512, SM_TOT>>>(gh, nullptr, dnh, dn_b, dn, y2, nullptr,
                                           256, 1152, 2304, 1, 5, 2, 0);
    // GN3 (sums dn + y2 partial) -> NCHW output
    k_gn<<<128, 256>>>(dn, y2, (float*)d_out, (__half*)nullptr,
                       gn3_g, gn3_b, 1024, 0, 1, 32);
}

// round 14
// speedup vs baseline: 1.0816x; 1.0216x over previous
#include <cuda_runtime.h>
#include <cuda_fp16.h>
#include <cstdint>
#include <math.h>

#define NB   4
#define CC   256
#define HP   66
#define LPIX 4096
#define NPIX 16384

// ======================= PTX helpers ========================================
__device__ __forceinline__ uint32_t smem_u32(const void* p) {
    uint32_t a;
    asm("{ .reg .u64 t; cvta.to.shared.u64 t, %1; cvt.u32.u64 %0, t; }" : "=r"(a) : "l"(p));
    return a;
}
#define CP_ASYNC16(dst, src, sz) \
    asm volatile("cp.async.cg.shared.global [%0], [%1], 16, %2;" \
                 :: "r"(dst), "l"(src), "r"(sz) : "memory")
#define CP_COMMIT() asm volatile("cp.async.commit_group;" ::: "memory")
#define CP_WAIT(n)  asm volatile("cp.async.wait_group %0;" :: "n"(n) : "memory")

#define LDSM4(r0, r1, r2, r3, a) \
    asm volatile("ldmatrix.sync.aligned.m8n8.x4.shared.b16 {%0,%1,%2,%3}, [%4];" \
        : "=r"(r0), "=r"(r1), "=r"(r2), "=r"(r3) : "r"(a))

#define MMA_F16(acc, A, B) \
    asm volatile("mma.sync.aligned.m16n8k16.row.col.f32.f16.f16.f32 " \
        "{%0,%1,%2,%3}, {%4,%5,%6,%7}, {%8,%9}, {%0,%1,%2,%3};" \
        : "+f"((acc)[0]), "+f"((acc)[1]), "+f"((acc)[2]), "+f"((acc)[3]) \
        : "r"((A)[0]), "r"((A)[1]), "r"((A)[2]), "r"((A)[3]), \
          "r"((B)[0]), "r"((B)[1]))

// ======================= scratch ============================================
__device__ __half g_xsh[NPIX * CC];
__device__ __half g_xp [NB * HP * HP * CC];          // padded x_proj, fp16
__device__ __half g_th [NPIX * CC];
__device__ float  g_om [NPIX * 216];
__device__ float  g_bom[216];
__device__ __half g_yh [NPIX * CC];
__device__ float  g_y2 [NPIX * CC];
__device__ __half g_gh [NPIX * CC];
__device__ float  g_dn [NB * 32 * 32 * CC];
// weights: [N, K] fp16 (hi only)
__device__ __half g_winh[256*256];
__device__ __half g_omh [216*256];
__device__ __half g_wouh[256*256];
__device__ __half g_c1h [256*2304];
__device__ __half g_dnh [256*2304];

// ======================= misc kernels =======================================
__device__ __forceinline__ void block_reduce2(float &a, float &b, float* sh) {
    int lane = threadIdx.x & 31, wid = threadIdx.x >> 5;
#pragma unroll
    for (int o = 16; o; o >>= 1) {
        a += __shfl_down_sync(0xffffffffu, a, o);
        b += __shfl_down_sync(0xffffffffu, b, o);
    }
    if (lane == 0) { sh[wid] = a; sh[8 + wid] = b; }
    __syncthreads();
    if (wid == 0) {
        a = (lane < 8) ? sh[lane] : 0.f;
        b = (lane < 8) ? sh[8 + lane] : 0.f;
#pragma unroll
        for (int o = 4; o; o >>= 1) {
            a += __shfl_down_sync(0xffffffffu, a, o);
            b += __shfl_down_sync(0xffffffffu, b, o);
        }
        if (lane == 0) { sh[16] = a; sh[17] = b; }
    }
    __syncthreads();
    a = sh[16]; b = sh[17];
}

__global__ void k_transpose(const float* __restrict__ x) {
    __shared__ float tile[32][33];
    int n  = blockIdx.z;
    int c0 = blockIdx.x * 32;
    int p0 = blockIdx.y * 32;
    int tx = threadIdx.x, ty = threadIdx.y;
#pragma unroll
    for (int j = 0; j < 32; j += 8)
        tile[ty + j][tx] = x[(size_t)(n * CC + c0 + ty + j) * LPIX + p0 + tx];
    __syncthreads();
#pragma unroll
    for (int j = 0; j < 32; j += 8) {
        size_t o = (size_t)(n * LPIX + p0 + ty + j) * CC + c0 + tx;
        g_xsh[o] = __float2half(tile[tx][ty + j]);
    }
}

// zero only the 1-pixel border of the padded fp16 buffer (interior overwritten)
__global__ void k_zero_border() {
    int i = blockIdx.x * 256 + threadIdx.x;     // 4 batches * 260 border px * 32 float4
    if (i >= 4 * 260 * 32) return;
    int c4 = i & 31;
    int b  = (i >> 5) % 260;
    int n  = i / (260 * 32);
    int y, x;
    if (b < 66)       { y = 0;       x = b; }
    else if (b < 132) { y = 65;      x = b - 66; }
    else if (b < 196) { y = b - 131; x = 0; }
    else              { y = b - 195; x = 65; }
    reinterpret_cast<float4*>(g_xp + ((size_t)(n * HP + y) * HP + x) * CC)[c4] =
        make_float4(0.f, 0.f, 0.f, 0.f);
}

// tiled transpose weight prep: w [K,N] fp32 -> Wh [N,K] fp16
__global__ void k_wprep(const float* __restrict__ w, __half* __restrict__ Wh, int K, int N) {
    __shared__ float tile[32][33];
    int k0 = blockIdx.x * 32, n0 = blockIdx.y * 32;
    int tx = threadIdx.x, ty = threadIdx.y;   // 32 x 8
#pragma unroll
    for (int j = 0; j < 32; j += 8) {
        int k = k0 + ty + j, n = n0 + tx;
        tile[ty + j][tx] = (k < K && n < N) ? w[(size_t)k * N + n] : 0.f;
    }
    __syncthreads();
#pragma unroll
    for (int j = 0; j < 32; j += 8) {
        int n = n0 + ty + j, k = k0 + tx;
        if (n < N && k < K)
            Wh[(size_t)n * K + k] = __float2half(tile[tx][ty + j]);
    }
}

__global__ void k_bias_cat(const float* __restrict__ b1, const float* __restrict__ b2) {
    int i = threadIdx.x;
    if (i < 144) g_bom[i] = b1[i];
    else if (i < 216) g_bom[i] = b2[i - 144];
}

__global__ void k_dw(const float* __restrict__ dww, const float* __restrict__ dwb,
                     const float* __restrict__ lng, const float* __restrict__ lnb)
{
    int pix = blockIdx.x;
    int c   = threadIdx.x;
    int n = pix >> 12, h = (pix >> 6) & 63, w = pix & 63;
    float acc = dwb[c];
#pragma unroll
    for (int kh = 0; kh < 3; kh++) {
        int y = h + kh - 1;
        if ((unsigned)y >= 64u) continue;
#pragma unroll
        for (int kw = 0; kw < 3; kw++) {
            int x = w + kw - 1;
            if ((unsigned)x >= 64u) continue;
            acc += __half2float(g_xsh[((size_t)((n * 64 + y) * 64 + x)) * 256 + c]) *
                   dww[(kh * 3 + kw) * 256 + c];
        }
    }
    __shared__ float sh[32];
    float s = acc, ss = acc * acc;
    block_reduce2(s, ss, sh);
    float mean = s * (1.f / 256.f);
    float var  = ss * (1.f / 256.f) - mean * mean;
    float rstd = rsqrtf(var + 1e-5f);
    float v = (acc - mean) * rstd * lng[c] + lnb[c];
    v = 0.5f * v * (1.f + erff(v * 0.70710678118654752440f));
    g_th[(size_t)pix * 256 + c] = __float2half(v);
}

__global__ void k_sample()
{
    int pix  = blockIdx.x;
    int g    = threadIdx.x >> 5;
    int lane = threadIdx.x & 31;
    int n = pix >> 12, h = (pix >> 6) & 63, w = pix & 63;

    const float* ml = g_om + (size_t)pix * 216 + 144 + g * 9;
    float e[9], mx = -1e30f, s = 0.f;
#pragma unroll
    for (int p = 0; p < 9; p++) mx = fmaxf(mx, ml[p]);
#pragma unroll
    for (int p = 0; p < 9; p++) { e[p] = expf(ml[p] - mx); s += e[p]; }
    float inv = 1.f / s;

    const float* off = g_om + (size_t)pix * 216 + g * 18;
    const __half* img = g_xp + (size_t)n * HP * HP * CC + g * 32 + lane;
    float acc = 0.f;
#pragma unroll
    for (int p = 0; p < 9; p++) {
        float px = (float)(w + p / 3) + off[2 * p];
        float py = (float)(h + p % 3) + off[2 * p + 1];
        float wgt = e[p] * inv;
        float x0f = floorf(px), y0f = floorf(py);
        int x0 = (int)x0f, y0 = (int)y0f;
        float fx = px - x0f, fy = py - y0f;
#pragma unroll
        for (int dy = 0; dy < 2; dy++) {
            int yy = y0 + dy;
            if ((unsigned)yy >= (unsigned)HP) continue;
            float wy = dy ? fy : 1.f - fy;
#pragma unroll
            for (int dx = 0; dx < 2; dx++) {
                int xx = x0 + dx;
                if ((unsigned)xx >= (unsigned)HP) continue;
                float wx = dx ? fx : 1.f - fx;
                acc += __half2float(img[((size_t)yy * HP + xx) * CC]) * (wx * wy * wgt);
            }
        }
    }
    g_yh[(size_t)pix * 256 + g * 32 + lane] = __float2half(acc);
}

// GroupNorm(32) [+SiLU]; optional second input summed in; fp32/NCHW and/or fp16 out
__global__ void k_gn(const float* __restrict__ in, const float* __restrict__ in2,
                     float* __restrict__ outf,
                     __half* __restrict__ oh,
                     const float* __restrict__ gamma, const float* __restrict__ beta,
                     int HWn, int do_silu, int out_nchw, int Wd)
{
    int n = blockIdx.x >> 5;
    int g = blockIdx.x & 31;
    int cnt = HWn * 8;
    const float* base  = in  + (size_t)n * HWn * 256 + g * 8;
    const float* base2 = in2 ? in2 + (size_t)n * HWn * 256 + g * 8 : nullptr;
    float s = 0.f, ss = 0.f;
    for (int i = threadIdx.x; i < cnt; i += 256) {
        size_t o = (size_t)(i >> 3) * 256 + (i & 7);
        float v = base[o];
        if (base2) v += base2[o];
        s += v; ss += v * v;
    }
    __shared__ float sh[32];
    block_reduce2(s, ss, sh);
    float mean = s / (float)cnt;
    float rstd = rsqrtf(ss / (float)cnt - mean * mean + 1e-5f);
    for (int i = threadIdx.x; i < cnt; i += 256) {
        int l = i >> 3, c = i & 7;
        size_t o = (size_t)l * 256 + c;
        float v = base[o];
        if (base2) v += base2[o];
        v = (v - mean) * rstd * gamma[g * 8 + c] + beta[g * 8 + c];
        if (do_silu) v = v * (1.f / (1.f + expf(-v)));
        if (outf) {
            if (out_nchw)
                outf[(((size_t)n * 256 + g * 8 + c) * Wd + (l / Wd)) * Wd + (l % Wd)] = v;
            else
                outf[((size_t)n * HWn + l) * 256 + g * 8 + c] = v;
        }
        if (oh)
            oh[((size_t)n * HWn + l) * 256 + g * 8 + c] = __float2half(v);
    }
}

// ======================= mma.sync fp16 GEMM ==================================
// 512 threads, 16 warps (4M x 4N), warp tile 32x32, CTA tile 128x128, BK=64.
// 2-term (Al!=null): (Ah+Al)*Bh, 4 stages (48KB ea), per-stage barrier
// 1-term (Al==null): Ah*Bh,      6 stages (32KB ea), ONE barrier per 2 stages
// padout: write fp16 into padded 66x66x256 buffer (CoutH)
#define MATB   16384
#define SM_TOT 196608

__global__ void __launch_bounds__(512, 1)
k_mma(const __half* __restrict__ Ah, const __half* __restrict__ Al,
      const __half* __restrict__ Bh,
      const float* __restrict__ bias, float* __restrict__ Cout, float* __restrict__ Cout2,
      __half* __restrict__ CoutH,
      int N, int Kloc, int Kfull, int mode, int owbits, int stride, int padout)
{
    extern __shared__ __align__(128) char smem[];
    const uint32_t sb = smem_u32(smem);
    const int tid = threadIdx.x;
    const int wid = tid >> 5, lane = tid & 31;
    const int g = lane >> 2, tg = lane & 3;
    const int warpM = wid & 3, warpN = wid >> 2;
    const int m0 = blockIdx.x * 128;
    const int n0 = blockIdx.y * 128;
    const int kb = blockIdx.z * Kloc;
    float* Cbase = (blockIdx.z == 0) ? Cout : Cout2;
    const float* bias_eff = (blockIdx.z == 0) ? bias : nullptr;
    const bool twoA  = (Al != nullptr);
    const int nmats  = twoA ? 3 : 2;
    const uint32_t stagesz = (uint32_t)nmats * MATB;
    const int S = Kloc >> 6;

    float acc[2][4][4];
#pragma unroll
    for (int i = 0; i < 2; i++)
#pragma unroll
        for (int j = 0; j < 4; j++)
#pragma unroll
            for (int r = 0; r < 4; r++) acc[i][j][r] = 0.f;

    auto fill = [&](int s, int st) {
        int gk = kb + (s << 6);
        int tap = gk >> 8, ci0 = gk & 255;
        int kh = tap / 3, kw = tap - 3 * kh;
        uint32_t stbase = sb + st * stagesz;
#pragma unroll 3
        for (int q = 0; q < 6; q++) {
            int cid = q * 512 + tid;           // 0..3071
            int mat = cid >> 10;
            if (mat >= nmats) break;
            int idx = cid & 1023;
            int r = idx >> 3, c = idx & 7;
            uint32_t dst = stbase + mat * MATB + r * 128 + ((c ^ (r & 7)) << 4);
            const __half* src;
            int sz = 16;
            if (mat != 1) {                     // A mats
                const __half* Ag = (mat == 0) ? Ah : Al;
                int m = m0 + r;
                if (mode == 0) {
                    src = Ag + (size_t)m * Kfull + gk + c * 8;
                } else {
                    int nn = m >> (2 * owbits);
                    int hw = m & ((1 << (2 * owbits)) - 1);
                    int ohh = hw >> owbits, oww = hw & ((1 << owbits) - 1);
                    int iy = ohh * stride + kh - 1, ix = oww * stride + kw - 1;
                    if ((unsigned)iy < 64u && (unsigned)ix < 64u)
                        src = Ag + ((size_t)((nn * 64 + iy) * 64 + ix)) * 256 + ci0 + c * 8;
                    else { src = Ag; sz = 0; }
                }
            } else {                            // B
                int n = n0 + r;
                if (n < N) src = Bh + (size_t)n * Kfull + gk + c * 8;
                else { src = Bh; sz = 0; }
            }
            CP_ASYNC16(dst, src, sz);
        }
    };

    const int lx = lane & 7;
    const uint32_t laneA_row = (uint32_t)(warpM * 32 + lx + ((lane >> 3) & 1) * 8) * 128;
    const uint32_t laneB_row = (uint32_t)(warpN * 32 + lx + ((lane >> 4) & 1) * 8) * 128;
    const int cselA = (lane >> 4) & 1;
    const int cselB = (lane >> 3) & 1;

    auto compute = [&](int st) {
        uint32_t bAh = sb + st * stagesz;
        uint32_t bBh = bAh + MATB;
        uint32_t bAl = bAh + 2 * MATB;
#pragma unroll
        for (int kk = 0; kk < 4; kk++) {
            uint32_t swzA = (uint32_t)(((kk * 2 + cselA) ^ lx) << 4);
            uint32_t swzB = (uint32_t)(((kk * 2 + cselB) ^ lx) << 4);
            uint32_t ah[2][4], al_[2][4], bh[4][2];
#pragma unroll
            for (int mi = 0; mi < 2; mi++) {
                LDSM4(ah[mi][0], ah[mi][1], ah[mi][2], ah[mi][3],
                      bAh + laneA_row + mi * 2048 + swzA);
                if (twoA)
                    LDSM4(al_[mi][0], al_[mi][1], al_[mi][2], al_[mi][3],
                          bAl + laneA_row + mi * 2048 + swzA);
            }
#pragma unroll
            for (int np = 0; np < 2; np++)
                LDSM4(bh[np*2][0], bh[np*2][1], bh[np*2+1][0], bh[np*2+1][1],
                      bBh + laneB_row + np * 2048 + swzB);
#pragma unroll
            for (int mi = 0; mi < 2; mi++)
#pragma unroll
                for (int ni = 0; ni < 4; ni++)
                    MMA_F16(acc[mi][ni], ah[mi], bh[ni]);
            if (twoA) {
#pragma unroll
                for (int mi = 0; mi < 2; mi++)
#pragma unroll
                    for (int ni = 0; ni < 4; ni++)
                        MMA_F16(acc[mi][ni], al_[mi], bh[ni]);
            }
        }
    };

    if (twoA) {
        // depth 4, per-stage barrier
        for (int s = 0; s < 3; s++) { if (s < S) fill(s, s); CP_COMMIT(); }
        int st = 0;
        for (int s = 0; s < S; s++) {
            CP_WAIT(2);
            __syncthreads();
            int stf = st + 3; if (stf >= 4) stf -= 4;
            if (s + 3 < S) fill(s + 3, stf);
            CP_COMMIT();
            compute(st);
            if (++st == 4) st = 0;
        }
    } else {
        // depth 6, one barrier per 2 stages (S is even for all 1-term calls)
        for (int s = 0; s < 4; s++) { if (s < S) fill(s, s); CP_COMMIT(); }
        int st = 0;
        for (int s = 0; s < S; s += 2) {
            CP_WAIT(2);
            __syncthreads();
            int f0 = st + 4; if (f0 >= 6) f0 -= 6;
            int f1 = st + 5; if (f1 >= 6) f1 -= 6;
            if (s + 4 < S) fill(s + 4, f0);
            CP_COMMIT();
            if (s + 5 < S) fill(s + 5, f1);
            CP_COMMIT();
            compute(st);
            int st1 = st + 1; if (st1 >= 6) st1 -= 6;
            compute(st1);
            st += 2; if (st >= 6) st -= 6;
        }
    }

    // ---- epilogue ----
#pragma unroll
    for (int mi = 0; mi < 2; mi++) {
        int mA = m0 + warpM * 32 + mi * 16 + g;
#pragma unroll
        for (int half = 0; half < 2; half++) {
            int m = mA + half * 8;
            if (padout) {
                int n = m >> 12, h = (m >> 6) & 63, w = m & 63;
                __half* orow = CoutH + ((size_t)(n * HP + h + 1) * HP + (w + 1)) * 256;
#pragma unroll
                for (int ni = 0; ni < 4; ni++) {
                    int nc = n0 + warpN * 32 + ni * 8 + tg * 2;
                    float v0 = acc[mi][ni][half * 2]     + bias[nc];
                    float v1 = acc[mi][ni][half * 2 + 1] + bias[nc + 1];
                    *reinterpret_cast<__half2*>(orow + nc) = __floats2half2_rn(v0, v1);
                }
            } else {
                float* orow = Cbase + (size_t)m * N;
#pragma unroll
                for (int ni = 0; ni < 4; ni++) {
                    int nc = n0 + warpN * 32 + ni * 8 + tg * 2;
                    float b0 = bias_eff ? bias_eff[nc < N ? nc : 0] : 0.f;
                    float b1 = bias_eff ? bias_eff[nc + 1 < N ? nc + 1 : 0] : 0.f;
                    if (nc < N)     orow[nc]     = acc[mi][ni][half * 2]     + b0;
                    if (nc + 1 < N) orow[nc + 1] = acc[mi][ni][half * 2 + 1] + b1;
                }
            }
        }
    }
}

// ======================= launch =============================================
extern "C" void kernel_launch(void* const* d_in, const int* in_sizes, int n_in,
                              void* d_out, int out_size)
{
    const float* x      = (const float*)d_in[0];
    const float* w_in   = (const float*)d_in[1];
    const float* b_in   = (const float*)d_in[2];
    const float* dw_w   = (const float*)d_in[3];
    const float* dw_b   = (const float*)d_in[4];
    const float* ln_g   = (const float*)d_in[5];
    const float* ln_b   = (const float*)d_in[6];
    const float* w_off  = (const float*)d_in[7];
    const float* b_off  = (const float*)d_in[8];
    const float* w_mask = (const float*)d_in[9];
    const float* b_mask = (const float*)d_in[10];
    const float* w_out  = (const float*)d_in[11];
    const float* b_out  = (const float*)d_in[12];
    const float* gn1_g  = (const float*)d_in[13];
    const float* gn1_b  = (const float*)d_in[14];
    const float* c1_w   = (const float*)d_in[15];
    const float* c1_b   = (const float*)d_in[16];
    const float* gn2_g  = (const float*)d_in[17];
    const float* gn2_b  = (const float*)d_in[18];
    const float* dn_w   = (const float*)d_in[19];
    const float* dn_b   = (const float*)d_in[20];
    const float* gn3_g  = (const float*)d_in[21];
    const float* gn3_b  = (const float*)d_in[22];

    cudaFuncSetAttribute(k_mma, cudaFuncAttributeMaxDynamicSharedMemorySize, SM_TOT);

    float *om, *bom, *y2, *dn;
    __half *xp, *xsh, *th, *yh, *gh;
    __half *winh, *omh, *wouh, *c1h, *dnh;
    cudaGetSymbolAddress((void**)&xp,  g_xp);
    cudaGetSymbolAddress((void**)&om,  g_om);
    cudaGetSymbolAddress((void**)&bom, g_bom);
    cudaGetSymbolAddress((void**)&y2,  g_y2);
    cudaGetSymbolAddress((void**)&dn,  g_dn);
    cudaGetSymbolAddress((void**)&xsh, g_xsh);
    cudaGetSymbolAddress((void**)&th,  g_th);
    cudaGetSymbolAddress((void**)&yh,  g_yh);
    cudaGetSymbolAddress((void**)&gh,  g_gh);
    cudaGetSymbolAddress((void**)&winh, g_winh);
    cudaGetSymbolAddress((void**)&omh,  g_omh);
    cudaGetSymbolAddress((void**)&wouh, g_wouh);
    cudaGetSymbolAddress((void**)&c1h,  g_c1h);  cudaGetSymbolAddress((void**)&dnh,  g_dnh);

    dim3 wblk(32, 8);
    k_transpose<<<dim3(8, 128, 4), wblk>>>(x);                                   // 0
    k_zero_border<<<130, 256>>>();                                               // 1
    k_wprep<<<dim3(8, 8), wblk>>>(w_in, winh, 256, 256);                         // 2
    // 3: input projection -> padded xp fp16 (1-term)   [PROFILED LAUNCH]
    k_mma<<<dim3(128, 2, 1), 512, SM_TOT>>>(xsh, nullptr, winh, b_in, nullptr, nullptr, xp,
                                            256, 256, 256, 0, 0, 0, 1);
    // remaining weight preps
    k_wprep<<<dim3(8, 5), wblk>>>(w_off,  omh,             256, 144);
    k_wprep<<<dim3(8, 3), wblk>>>(w_mask, omh + 144 * 256, 256, 72);
    k_bias_cat<<<1, 256>>>(b_off, b_mask);
    k_wprep<<<dim3(8, 8),  wblk>>>(w_out, wouh, 256, 256);
    k_wprep<<<dim3(72, 8), wblk>>>(c1_w, c1h, 2304, 256);
    k_wprep<<<dim3(72, 8), wblk>>>(dn_w, dnh, 2304, 256);
    // depthwise + LN + GELU -> t (fp16)
    k_dw<<<NPIX, 256>>>(dw_w, dw_b, ln_g, ln_b);
    // fused offset+mask projection (N=216, 1-term)
    k_mma<<<dim3(128, 2, 1), 512, SM_TOT>>>(th, nullptr, omh, bom, om, nullptr, nullptr,
                                            216, 256, 256, 0, 0, 0, 0);
    // deformable sampling -> y (fp16)
    k_sample<<<NPIX, 256>>>();
    // output projection -> y2 (1-term)
    k_mma<<<dim3(128, 2, 1), 512, SM_TOT>>>(yh, nullptr, wouh, b_out, y2, nullptr, nullptr,
                                            256, 256, 256, 0, 0, 0, 0);
    // GN1 + SiLU -> fp16 (hi only)
    k_gn<<<128, 256>>>(y2, nullptr, (float*)nullptr, gh, gn1_g, gn1_b, 4096, 1, 0, 64);
    // conv1 3x3 implicit im2col (K=2304, 1-term fp16, paired stages) -> y2
    k_mma<<<dim3(128, 2, 1), 512, SM_TOT>>>(gh, nullptr, c1h, c1_b, y2, nullptr, nullptr,
                                            256, 2304, 2304, 1, 6, 1, 0);
    // GN2 + SiLU -> fp16 (hi only)
    k_gn<<<128, 256>>>(y2, nullptr, (float*)nullptr, gh, gn2_g, gn2_b, 4096, 1, 0, 64);
    // down conv 3x3 stride2 (1-term, K-split z=2: dn + partial in y2)
    k_mma<<<dim3(32, 2, 2), 512, SM_TOT>>>(gh, nullptr, dnh, dn_b, dn, y2, nullptr,
                                           256, 1152, 2304, 1, 5, 2, 0);
    // GN3 (sums dn + y2 partial) -> NCHW output
    k_gn<<<128, 256>>>(dn, y2, (float*)d_out, (__half*)nullptr,
                       gn3_g, gn3_b, 1024, 0, 1, 32);
}

// round 15
// speedup vs baseline: 1.2360x; 1.1428x over previous
#include <cuda_runtime.h>
#include <cuda_fp16.h>
#include <cstdint>
#include <math.h>

#define NB   4
#define CC   256
#define HP   66
#define LPIX 4096
#define NPIX 16384

// ======================= PTX helpers ========================================
__device__ __forceinline__ uint32_t smem_u32(const void* p) {
    uint32_t a;
    asm("{ .reg .u64 t; cvta.to.shared.u64 t, %1; cvt.u32.u64 %0, t; }" : "=r"(a) : "l"(p));
    return a;
}
#define CP_ASYNC16(dst, src, sz) \
    asm volatile("cp.async.cg.shared.global [%0], [%1], 16, %2;" \
                 :: "r"(dst), "l"(src), "r"(sz) : "memory")
#define CP_COMMIT() asm volatile("cp.async.commit_group;" ::: "memory")
#define CP_WAIT(n)  asm volatile("cp.async.wait_group %0;" :: "n"(n) : "memory")

#define LDSM4(r0, r1, r2, r3, a) \
    asm volatile("ldmatrix.sync.aligned.m8n8.x4.shared.b16 {%0,%1,%2,%3}, [%4];" \
        : "=r"(r0), "=r"(r1), "=r"(r2), "=r"(r3) : "r"(a))

#define MMA_F16(acc, A, B) \
    asm volatile("mma.sync.aligned.m16n8k16.row.col.f32.f16.f16.f32 " \
        "{%0,%1,%2,%3}, {%4,%5,%6,%7}, {%8,%9}, {%0,%1,%2,%3};" \
        : "+f"((acc)[0]), "+f"((acc)[1]), "+f"((acc)[2]), "+f"((acc)[3]) \
        : "r"((A)[0]), "r"((A)[1]), "r"((A)[2]), "r"((A)[3]), \
          "r"((B)[0]), "r"((B)[1]))

// ======================= scratch ============================================
__device__ __half g_xsh[NPIX * CC];
__device__ __half g_xp [NB * HP * HP * CC];          // padded x_proj, fp16
__device__ __half g_th [NPIX * CC];
__device__ float  g_om [NPIX * 216];
__device__ float  g_bom[216];
__device__ __half g_yh [NPIX * CC];
__device__ float  g_y2 [NPIX * CC];
__device__ __half g_gh [NPIX * CC];
__device__ float  g_dn [NB * 32 * 32 * CC];
// weights: [N, K] fp16 (hi only)
__device__ __half g_winh[256*256];
__device__ __half g_omh [216*256];
__device__ __half g_wouh[256*256];
__device__ __half g_c1h [256*2304];
__device__ __half g_dnh [256*2304];

// ======================= misc kernels =======================================
__device__ __forceinline__ void block_reduce2(float &a, float &b, float* sh) {
    int lane = threadIdx.x & 31, wid = threadIdx.x >> 5;
#pragma unroll
    for (int o = 16; o; o >>= 1) {
        a += __shfl_down_sync(0xffffffffu, a, o);
        b += __shfl_down_sync(0xffffffffu, b, o);
    }
    if (lane == 0) { sh[wid] = a; sh[8 + wid] = b; }
    __syncthreads();
    if (wid == 0) {
        a = (lane < 8) ? sh[lane] : 0.f;
        b = (lane < 8) ? sh[8 + lane] : 0.f;
#pragma unroll
        for (int o = 4; o; o >>= 1) {
            a += __shfl_down_sync(0xffffffffu, a, o);
            b += __shfl_down_sync(0xffffffffu, b, o);
        }
        if (lane == 0) { sh[16] = a; sh[17] = b; }
    }
    __syncthreads();
    a = sh[16]; b = sh[17];
}

__global__ void k_transpose(const float* __restrict__ x) {
    __shared__ float tile[32][33];
    int n  = blockIdx.z;
    int c0 = blockIdx.x * 32;
    int p0 = blockIdx.y * 32;
    int tx = threadIdx.x, ty = threadIdx.y;
#pragma unroll
    for (int j = 0; j < 32; j += 8)
        tile[ty + j][tx] = x[(size_t)(n * CC + c0 + ty + j) * LPIX + p0 + tx];
    __syncthreads();
#pragma unroll
    for (int j = 0; j < 32; j += 8) {
        size_t o = (size_t)(n * LPIX + p0 + ty + j) * CC + c0 + tx;
        g_xsh[o] = __float2half(tile[tx][ty + j]);
    }
}

// ======================= mega-prep: all weight preps + border zero + bias ===
__device__ __forceinline__ void wprep_task(const float* __restrict__ w,
                                           __half* __restrict__ Wh,
                                           int K, int N, int bx, int by,
                                           float (*tile)[33]) {
    int tx = threadIdx.x & 31, ty = threadIdx.x >> 5;   // 32 x 8
    int k0 = bx * 32, n0 = by * 32;
#pragma unroll
    for (int j = 0; j < 32; j += 8) {
        int k = k0 + ty + j, n = n0 + tx;
        tile[ty + j][tx] = (k < K && n < N) ? w[(size_t)k * N + n] : 0.f;
    }
    __syncthreads();
#pragma unroll
    for (int j = 0; j < 32; j += 8) {
        int n = n0 + ty + j, k = k0 + tx;
        if (n < N && k < K)
            Wh[(size_t)n * K + k] = __float2half(tile[tx][ty + j]);
    }
}

__global__ void k_prep(const float* __restrict__ w_in,  const float* __restrict__ w_off,
                       const float* __restrict__ w_mask, const float* __restrict__ w_out,
                       const float* __restrict__ c1_w,  const float* __restrict__ dn_w,
                       const float* __restrict__ b_off, const float* __restrict__ b_mask)
{
    __shared__ float tile[32][33];
    int id = blockIdx.x;
    if (id < 64)        { wprep_task(w_in,  g_winh, 256, 256, id & 7, id >> 3, tile); return; }
    id -= 64;
    if (id < 40)        { wprep_task(w_off, g_omh,  256, 144, id & 7, id >> 3, tile); return; }
    id -= 40;
    if (id < 24)        { wprep_task(w_mask, g_omh + 144 * 256, 256, 72, id & 7, id >> 3, tile); return; }
    id -= 24;
    if (id < 64)        { wprep_task(w_out, g_wouh, 256, 256, id & 7, id >> 3, tile); return; }
    id -= 64;
    if (id < 576)       { wprep_task(c1_w,  g_c1h, 2304, 256, id % 72, id / 72, tile); return; }
    id -= 576;
    if (id < 576)       { wprep_task(dn_w,  g_dnh, 2304, 256, id % 72, id / 72, tile); return; }
    id -= 576;
    if (id < 130) {
        int i = id * 256 + threadIdx.x;       // 4 batches * 260 border px * 32 float4
        if (i < 4 * 260 * 32) {
            int c4 = i & 31;
            int b  = (i >> 5) % 260;
            int n  = i / (260 * 32);
            int y, x;
            if (b < 66)       { y = 0;       x = b; }
            else if (b < 132) { y = 65;      x = b - 66; }
            else if (b < 196) { y = b - 131; x = 0; }
            else              { y = b - 195; x = 65; }
            reinterpret_cast<float4*>(g_xp + ((size_t)(n * HP + y) * HP + x) * CC)[c4] =
                make_float4(0.f, 0.f, 0.f, 0.f);
        }
        return;
    }
    // last block: bias concat
    int i = threadIdx.x;
    if (i < 144) g_bom[i] = b_off[i];
    else if (i < 216) g_bom[i] = b_mask[i - 144];
}

// ======================= depthwise + LN + GELU (4 pixels per block) =========
__global__ void k_dw(const float* __restrict__ dww, const float* __restrict__ dwb,
                     const float* __restrict__ lng, const float* __restrict__ lnb)
{
    int blk = blockIdx.x;                 // 4096 blocks
    int c   = threadIdx.x;
    int n  = blk >> 10;
    int h  = (blk >> 4) & 63;
    int w0 = (blk & 15) * 4;

    float v[3][6];
#pragma unroll
    for (int r = 0; r < 3; r++) {
        int y = h + r - 1;
#pragma unroll
        for (int j = 0; j < 6; j++) {
            int x = w0 + j - 1;
            v[r][j] = ((unsigned)y < 64u && (unsigned)x < 64u)
                ? __half2float(g_xsh[((size_t)((n * 64 + y) * 64 + x)) * 256 + c]) : 0.f;
        }
    }
    float wgt[9];
#pragma unroll
    for (int t = 0; t < 9; t++) wgt[t] = dww[t * 256 + c];
    float bias = dwb[c], gam = lng[c], bet = lnb[c];

    float acc[4];
#pragma unroll
    for (int p = 0; p < 4; p++) {
        float a = bias;
#pragma unroll
        for (int kh = 0; kh < 3; kh++)
#pragma unroll
            for (int kw = 0; kw < 3; kw++)
                a += v[kh][p + kw] * wgt[kh * 3 + kw];
        acc[p] = a;
    }

    __shared__ float sh[32];
#pragma unroll
    for (int p = 0; p < 4; p++) {
        float s = acc[p], ss = acc[p] * acc[p];
        block_reduce2(s, ss, sh);
        float mean = s * (1.f / 256.f);
        float var  = ss * (1.f / 256.f) - mean * mean;
        float rstd = rsqrtf(var + 1e-5f);
        float val = (acc[p] - mean) * rstd * gam + bet;
        val = 0.5f * val * (1.f + erff(val * 0.70710678118654752440f));
        g_th[((size_t)((n * 64 + h) * 64 + w0 + p)) * 256 + c] = __float2half(val);
    }
}

__global__ void k_sample()
{
    int pix  = blockIdx.x;
    int g    = threadIdx.x >> 5;
    int lane = threadIdx.x & 31;
    int n = pix >> 12, h = (pix >> 6) & 63, w = pix & 63;

    const float* ml = g_om + (size_t)pix * 216 + 144 + g * 9;
    float e[9], mx = -1e30f, s = 0.f;
#pragma unroll
    for (int p = 0; p < 9; p++) mx = fmaxf(mx, ml[p]);
#pragma unroll
    for (int p = 0; p < 9; p++) { e[p] = expf(ml[p] - mx); s += e[p]; }
    float inv = 1.f / s;

    const float* off = g_om + (size_t)pix * 216 + g * 18;
    const __half* img = g_xp + (size_t)n * HP * HP * CC + g * 32 + lane;
    float acc = 0.f;
#pragma unroll
    for (int p = 0; p < 9; p++) {
        float px = (float)(w + p / 3) + off[2 * p];
        float py = (float)(h + p % 3) + off[2 * p + 1];
        float wgt = e[p] * inv;
        float x0f = floorf(px), y0f = floorf(py);
        int x0 = (int)x0f, y0 = (int)y0f;
        float fx = px - x0f, fy = py - y0f;
#pragma unroll
        for (int dy = 0; dy < 2; dy++) {
            int yy = y0 + dy;
            if ((unsigned)yy >= (unsigned)HP) continue;
            float wy = dy ? fy : 1.f - fy;
#pragma unroll
            for (int dx = 0; dx < 2; dx++) {
                int xx = x0 + dx;
                if ((unsigned)xx >= (unsigned)HP) continue;
                float wx = dx ? fx : 1.f - fx;
                acc += __half2float(img[((size_t)yy * HP + xx) * CC]) * (wx * wy * wgt);
            }
        }
    }
    g_yh[(size_t)pix * 256 + g * 32 + lane] = __float2half(acc);
}

// GroupNorm(32) [+SiLU]; optional second input summed; values cached in smem
__global__ void k_gn(const float* __restrict__ in, const float* __restrict__ in2,
                     float* __restrict__ outf,
                     __half* __restrict__ oh,
                     const float* __restrict__ gamma, const float* __restrict__ beta,
                     int HWn, int do_silu, int out_nchw, int Wd)
{
    extern __shared__ float cache[];
    int n = blockIdx.x >> 5;
    int g = blockIdx.x & 31;
    int cnt = HWn * 8;
    const float* base  = in  + (size_t)n * HWn * 256 + g * 8;
    const float* base2 = in2 ? in2 + (size_t)n * HWn * 256 + g * 8 : nullptr;
    float s = 0.f, ss = 0.f;
    for (int i = threadIdx.x; i < cnt; i += 256) {
        size_t o = (size_t)(i >> 3) * 256 + (i & 7);
        float v = base[o];
        if (base2) v += base2[o];
        cache[i] = v;
        s += v; ss += v * v;
    }
    __shared__ float sh[32];
    block_reduce2(s, ss, sh);
    float mean = s / (float)cnt;
    float rstd = rsqrtf(ss / (float)cnt - mean * mean + 1e-5f);
    for (int i = threadIdx.x; i < cnt; i += 256) {
        int l = i >> 3, c = i & 7;
        float v = cache[i];
        v = (v - mean) * rstd * gamma[g * 8 + c] + beta[g * 8 + c];
        if (do_silu) v = v * (1.f / (1.f + expf(-v)));
        if (outf) {
            if (out_nchw)
                outf[(((size_t)n * 256 + g * 8 + c) * Wd + (l / Wd)) * Wd + (l % Wd)] = v;
            else
                outf[((size_t)n * HWn + l) * 256 + g * 8 + c] = v;
        }
        if (oh)
            oh[((size_t)n * HWn + l) * 256 + g * 8 + c] = __float2half(v);
    }
}

// ======================= mma.sync fp16 GEMM ==================================
// 512 threads, 16 warps (4M x 4N), warp tile 32x32, CTA tile 128x128, BK=64.
// 2-term (Al!=null): (Ah+Al)*Bh, 4 stages (48KB ea), per-stage barrier
// 1-term (Al==null): Ah*Bh,      6 stages (32KB ea), ONE barrier per 2 stages
// padout: write fp16 into padded 66x66x256 buffer (CoutH)
#define MATB   16384
#define SM_TOT 196608

__global__ void __launch_bounds__(512, 1)
k_mma(const __half* __restrict__ Ah, const __half* __restrict__ Al,
      const __half* __restrict__ Bh,
      const float* __restrict__ bias, float* __restrict__ Cout, float* __restrict__ Cout2,
      __half* __restrict__ CoutH,
      int N, int Kloc, int Kfull, int mode, int owbits, int stride, int padout)
{
    extern __shared__ __align__(128) char smem[];
    const uint32_t sb = smem_u32(smem);
    const int tid = threadIdx.x;
    const int wid = tid >> 5, lane = tid & 31;
    const int g = lane >> 2, tg = lane & 3;
    const int warpM = wid & 3, warpN = wid >> 2;
    const int m0 = blockIdx.x * 128;
    const int n0 = blockIdx.y * 128;
    const int kb = blockIdx.z * Kloc;
    float* Cbase = (blockIdx.z == 0) ? Cout : Cout2;
    const float* bias_eff = (blockIdx.z == 0) ? bias : nullptr;
    const bool twoA  = (Al != nullptr);
    const int nmats  = twoA ? 3 : 2;
    const uint32_t stagesz = (uint32_t)nmats * MATB;
    const int S = Kloc >> 6;

    float acc[2][4][4];
#pragma unroll
    for (int i = 0; i < 2; i++)
#pragma unroll
        for (int j = 0; j < 4; j++)
#pragma unroll
            for (int r = 0; r < 4; r++) acc[i][j][r] = 0.f;

    auto fill = [&](int s, int st) {
        int gk = kb + (s << 6);
        int tap = gk >> 8, ci0 = gk & 255;
        int kh = tap / 3, kw = tap - 3 * kh;
        uint32_t stbase = sb + st * stagesz;
#pragma unroll 3
        for (int q = 0; q < 6; q++) {
            int cid = q * 512 + tid;           // 0..3071
            int mat = cid >> 10;
            if (mat >= nmats) break;
            int idx = cid & 1023;
            int r = idx >> 3, c = idx & 7;
            uint32_t dst = stbase + mat * MATB + r * 128 + ((c ^ (r & 7)) << 4);
            const __half* src;
            int sz = 16;
            if (mat != 1) {                     // A mats
                const __half* Ag = (mat == 0) ? Ah : Al;
                int m = m0 + r;
                if (mode == 0) {
                    src = Ag + (size_t)m * Kfull + gk + c * 8;
                } else {
                    int nn = m >> (2 * owbits);
                    int hw = m & ((1 << (2 * owbits)) - 1);
                    int ohh = hw >> owbits, oww = hw & ((1 << owbits) - 1);
                    int iy = ohh * stride + kh - 1, ix = oww * stride + kw - 1;
                    if ((unsigned)iy < 64u && (unsigned)ix < 64u)
                        src = Ag + ((size_t)((nn * 64 + iy) * 64 + ix)) * 256 + ci0 + c * 8;
                    else { src = Ag; sz = 0; }
                }
            } else {                            // B
                int n = n0 + r;
                if (n < N) src = Bh + (size_t)n * Kfull + gk + c * 8;
                else { src = Bh; sz = 0; }
            }
            CP_ASYNC16(dst, src, sz);
        }
    };

    const int lx = lane & 7;
    const uint32_t laneA_row = (uint32_t)(warpM * 32 + lx + ((lane >> 3) & 1) * 8) * 128;
    const uint32_t laneB_row = (uint32_t)(warpN * 32 + lx + ((lane >> 4) & 1) * 8) * 128;
    const int cselA = (lane >> 4) & 1;
    const int cselB = (lane >> 3) & 1;

    auto compute = [&](int st) {
        uint32_t bAh = sb + st * stagesz;
        uint32_t bBh = bAh + MATB;
        uint32_t bAl = bAh + 2 * MATB;
#pragma unroll
        for (int kk = 0; kk < 4; kk++) {
            uint32_t swzA = (uint32_t)(((kk * 2 + cselA) ^ lx) << 4);
            uint32_t swzB = (uint32_t)(((kk * 2 + cselB) ^ lx) << 4);
            uint32_t ah[2][4], al_[2][4], bh[4][2];
#pragma unroll
            for (int mi = 0; mi < 2; mi++) {
                LDSM4(ah[mi][0], ah[mi][1], ah[mi][2], ah[mi][3],
                      bAh + laneA_row + mi * 2048 + swzA);
                if (twoA)
                    LDSM4(al_[mi][0], al_[mi][1], al_[mi][2], al_[mi][3],
                          bAl + laneA_row + mi * 2048 + swzA);
            }
#pragma unroll
            for (int np = 0; np < 2; np++)
                LDSM4(bh[np*2][0], bh[np*2][1], bh[np*2+1][0], bh[np*2+1][1],
                      bBh + laneB_row + np * 2048 + swzB);
#pragma unroll
            for (int mi = 0; mi < 2; mi++)
#pragma unroll
                for (int ni = 0; ni < 4; ni++)
                    MMA_F16(acc[mi][ni], ah[mi], bh[ni]);
            if (twoA) {
#pragma unroll
                for (int mi = 0; mi < 2; mi++)
#pragma unroll
                    for (int ni = 0; ni < 4; ni++)
                        MMA_F16(acc[mi][ni], al_[mi], bh[ni]);
            }
        }
    };

    if (twoA) {
        // depth 4, per-stage barrier
        for (int s = 0; s < 3; s++) { if (s < S) fill(s, s); CP_COMMIT(); }
        int st = 0;
        for (int s = 0; s < S; s++) {
            CP_WAIT(2);
            __syncthreads();
            int stf = st + 3; if (stf >= 4) stf -= 4;
            if (s + 3 < S) fill(s + 3, stf);
            CP_COMMIT();
            compute(st);
            if (++st == 4) st = 0;
        }
    } else {
        // depth 6, one barrier per 2 stages (S is even for all 1-term calls)
        for (int s = 0; s < 4; s++) { if (s < S) fill(s, s); CP_COMMIT(); }
        int st = 0;
        for (int s = 0; s < S; s += 2) {
            CP_WAIT(2);
            __syncthreads();
            int f0 = st + 4; if (f0 >= 6) f0 -= 6;
            int f1 = st + 5; if (f1 >= 6) f1 -= 6;
            if (s + 4 < S) fill(s + 4, f0);
            CP_COMMIT();
            if (s + 5 < S) fill(s + 5, f1);
            CP_COMMIT();
            compute(st);
            int st1 = st + 1; if (st1 >= 6) st1 -= 6;
            compute(st1);
            st += 2; if (st >= 6) st -= 6;
        }
    }

    // ---- epilogue ----
#pragma unroll
    for (int mi = 0; mi < 2; mi++) {
        int mA = m0 + warpM * 32 + mi * 16 + g;
#pragma unroll
        for (int half = 0; half < 2; half++) {
            int m = mA + half * 8;
            if (padout) {
                int n = m >> 12, h = (m >> 6) & 63, w = m & 63;
                __half* orow = CoutH + ((size_t)(n * HP + h + 1) * HP + (w + 1)) * 256;
#pragma unroll
                for (int ni = 0; ni < 4; ni++) {
                    int nc = n0 + warpN * 32 + ni * 8 + tg * 2;
                    float v0 = acc[mi][ni][half * 2]     + bias[nc];
                    float v1 = acc[mi][ni][half * 2 + 1] + bias[nc + 1];
                    *reinterpret_cast<__half2*>(orow + nc) = __floats2half2_rn(v0, v1);
                }
            } else {
                float* orow = Cbase + (size_t)m * N;
#pragma unroll
                for (int ni = 0; ni < 4; ni++) {
                    int nc = n0 + warpN * 32 + ni * 8 + tg * 2;
                    float b0 = bias_eff ? bias_eff[nc < N ? nc : 0] : 0.f;
                    float b1 = bias_eff ? bias_eff[nc + 1 < N ? nc + 1 : 0] : 0.f;
                    if (nc < N)     orow[nc]     = acc[mi][ni][half * 2]     + b0;
                    if (nc + 1 < N) orow[nc + 1] = acc[mi][ni][half * 2 + 1] + b1;
                }
            }
        }
    }
}

// ======================= launch =============================================
extern "C" void kernel_launch(void* const* d_in, const int* in_sizes, int n_in,
                              void* d_out, int out_size)
{
    const float* x      = (const float*)d_in[0];
    const float* w_in   = (const float*)d_in[1];
    const float* b_in   = (const float*)d_in[2];
    const float* dw_w   = (const float*)d_in[3];
    const float* dw_b   = (const float*)d_in[4];
    const float* ln_g   = (const float*)d_in[5];
    const float* ln_b   = (const float*)d_in[6];
    const float* w_off  = (const float*)d_in[7];
    const float* b_off  = (const float*)d_in[8];
    const float* w_mask = (const float*)d_in[9];
    const float* b_mask = (const float*)d_in[10];
    const float* w_out  = (const float*)d_in[11];
    const float* b_out  = (const float*)d_in[12];
    const float* gn1_g  = (const float*)d_in[13];
    const float* gn1_b  = (const float*)d_in[14];
    const float* c1_w   = (const float*)d_in[15];
    const float* c1_b   = (const float*)d_in[16];
    const float* gn2_g  = (const float*)d_in[17];
    const float* gn2_b  = (const float*)d_in[18];
    const float* dn_w   = (const float*)d_in[19];
    const float* dn_b   = (const float*)d_in[20];
    const float* gn3_g  = (const float*)d_in[21];
    const float* gn3_b  = (const float*)d_in[22];

    cudaFuncSetAttribute(k_mma, cudaFuncAttributeMaxDynamicSharedMemorySize, SM_TOT);
    cudaFuncSetAttribute(k_gn,  cudaFuncAttributeMaxDynamicSharedMemorySize, 131072);

    float *om, *bom, *y2, *dn;
    __half *xp, *xsh, *th, *yh, *gh;
    __half *winh, *omh, *wouh, *c1h, *dnh;
    cudaGetSymbolAddress((void**)&xp,  g_xp);
    cudaGetSymbolAddress((void**)&om,  g_om);
    cudaGetSymbolAddress((void**)&bom, g_bom);
    cudaGetSymbolAddress((void**)&y2,  g_y2);
    cudaGetSymbolAddress((void**)&dn,  g_dn);
    cudaGetSymbolAddress((void**)&xsh, g_xsh);
    cudaGetSymbolAddress((void**)&th,  g_th);
    cudaGetSymbolAddress((void**)&yh,  g_yh);
    cudaGetSymbolAddress((void**)&gh,  g_gh);
    cudaGetSymbolAddress((void**)&winh, g_winh);
    cudaGetSymbolAddress((void**)&omh,  g_omh);
    cudaGetSymbolAddress((void**)&wouh, g_wouh);
    cudaGetSymbolAddress((void**)&c1h,  g_c1h);  cudaGetSymbolAddress((void**)&dnh,  g_dnh);

    // 0: NCHW -> NHWC fp16
    k_transpose<<<dim3(8, 128, 4), dim3(32, 8)>>>(x);
    // 1: all weight preps + xp border zero + bias concat (single launch)
    k_prep<<<1475, 256>>>(w_in, w_off, w_mask, w_out, c1_w, dn_w, b_off, b_mask);
    // 2: input projection -> padded xp fp16 (1-term)
    k_mma<<<dim3(128, 2, 1), 512, SM_TOT>>>(xsh, nullptr, winh, b_in, nullptr, nullptr, xp,
                                            256, 256, 256, 0, 0, 0, 1);
    // 3: depthwise + LN + GELU -> t (fp16), 4 pixels/block
    k_dw<<<4096, 256>>>(dw_w, dw_b, ln_g, ln_b);
    // 4: fused offset+mask projection (N=216, 1-term)
    k_mma<<<dim3(128, 2, 1), 512, SM_TOT>>>(th, nullptr, omh, bom, om, nullptr, nullptr,
                                            216, 256, 256, 0, 0, 0, 0);
    // 5: deformable sampling -> y (fp16)
    k_sample<<<NPIX, 256>>>();
    // 6: output projection -> y2 (1-term)
    k_mma<<<dim3(128, 2, 1), 512, SM_TOT>>>(yh, nullptr, wouh, b_out, y2, nullptr, nullptr,
                                            256, 256, 256, 0, 0, 0, 0);
    // 7: GN1 + SiLU -> fp16 (smem-cached)
    k_gn<<<128, 256, 131072>>>(y2, nullptr, (float*)nullptr, gh, gn1_g, gn1_b, 4096, 1, 0, 64);
    // 8: conv1 3x3 implicit im2col (K=2304, 1-term, paired stages) -> y2
    k_mma<<<dim3(128, 2, 1), 512, SM_TOT>>>(gh, nullptr, c1h, c1_b, y2, nullptr, nullptr,
                                            256, 2304, 2304, 1, 6, 1, 0);
    // 9: GN2 + SiLU -> fp16 (smem-cached)
    k_gn<<<128, 256, 131072>>>(y2, nullptr, (float*)nullptr, gh, gn2_g, gn2_b, 4096, 1, 0, 64);
    // 10: down conv 3x3 stride2 (1-term, K-split z=2: dn + partial in y2)
    k_mma<<<dim3(32, 2, 2), 512, SM_TOT>>>(gh, nullptr, dnh, dn_b, dn, y2, nullptr,
                                           256, 1152, 2304, 1, 5, 2, 0);
    // 11: GN3 (sums dn + y2 partial, smem-cached) -> NCHW output
    k_gn<<<128, 256, 32768>>>(dn, y2, (float*)d_out, (__half*)nullptr,
                              gn3_g, gn3_b, 1024, 0, 1, 32);
}

// round 16
// speedup vs baseline: 1.2436x; 1.0062x over previous
#include <cuda_runtime.h>
#include <cuda_fp16.h>
#include <cstdint>
#include <math.h>

#define NB   4
#define CC   256
#define HP   66
#define LPIX 4096
#define NPIX 16384

// ======================= PTX helpers ========================================
__device__ __forceinline__ uint32_t smem_u32(const void* p) {
    uint32_t a;
    asm("{ .reg .u64 t; cvta.to.shared.u64 t, %1; cvt.u32.u64 %0, t; }" : "=r"(a) : "l"(p));
    return a;
}
#define CP_ASYNC16(dst, src, sz) \
    asm volatile("cp.async.cg.shared.global [%0], [%1], 16, %2;" \
                 :: "r"(dst), "l"(src), "r"(sz) : "memory")
#define CP_COMMIT() asm volatile("cp.async.commit_group;" ::: "memory")
#define CP_WAIT(n)  asm volatile("cp.async.wait_group %0;" :: "n"(n) : "memory")

#define LDSM4(r0, r1, r2, r3, a) \
    asm volatile("ldmatrix.sync.aligned.m8n8.x4.shared.b16 {%0,%1,%2,%3}, [%4];" \
        : "=r"(r0), "=r"(r1), "=r"(r2), "=r"(r3) : "r"(a))

#define MMA_F16(acc, A, B) \
    asm volatile("mma.sync.aligned.m16n8k16.row.col.f32.f16.f16.f32 " \
        "{%0,%1,%2,%3}, {%4,%5,%6,%7}, {%8,%9}, {%0,%1,%2,%3};" \
        : "+f"((acc)[0]), "+f"((acc)[1]), "+f"((acc)[2]), "+f"((acc)[3]) \
        : "r"((A)[0]), "r"((A)[1]), "r"((A)[2]), "r"((A)[3]), \
          "r"((B)[0]), "r"((B)[1]))

// ======================= scratch ============================================
__device__ __half g_xsh[NPIX * CC];
__device__ __half g_xp [NB * HP * HP * CC];          // padded x_proj, fp16
__device__ __half g_th [NPIX * CC];
__device__ float  g_om [NPIX * 216];
__device__ float  g_bom[216];
__device__ __half g_yh [NPIX * CC];
__device__ float  g_y2 [NPIX * CC];
__device__ __half g_gh [NPIX * CC];
__device__ float  g_dn [NB * 32 * 32 * CC];
// weights: [N, K] fp16 (hi only)
__device__ __half g_winh[256*256];
__device__ __half g_omh [216*256];
__device__ __half g_wouh[256*256];
__device__ __half g_c1h [256*2304];
__device__ __half g_dnh [256*2304];

// ======================= misc ===============================================
__device__ __forceinline__ void block_reduce2(float &a, float &b, float* sh) {
    int lane = threadIdx.x & 31, wid = threadIdx.x >> 5;
#pragma unroll
    for (int o = 16; o; o >>= 1) {
        a += __shfl_down_sync(0xffffffffu, a, o);
        b += __shfl_down_sync(0xffffffffu, b, o);
    }
    if (lane == 0) { sh[wid] = a; sh[8 + wid] = b; }
    __syncthreads();
    if (wid == 0) {
        a = (lane < 8) ? sh[lane] : 0.f;
        b = (lane < 8) ? sh[8 + lane] : 0.f;
#pragma unroll
        for (int o = 4; o; o >>= 1) {
            a += __shfl_down_sync(0xffffffffu, a, o);
            b += __shfl_down_sync(0xffffffffu, b, o);
        }
        if (lane == 0) { sh[16] = a; sh[17] = b; }
    }
    __syncthreads();
    a = sh[16]; b = sh[17];
}

// ======================= mega-prep: transpose + weight preps + border + bias =
__device__ __forceinline__ void wprep_task(const float* __restrict__ w,
                                           __half* __restrict__ Wh,
                                           int K, int N, int bx, int by,
                                           float (*tile)[33]) {
    int tx = threadIdx.x & 31, ty = threadIdx.x >> 5;   // 32 x 8
    int k0 = bx * 32, n0 = by * 32;
#pragma unroll
    for (int j = 0; j < 32; j += 8) {
        int k = k0 + ty + j, n = n0 + tx;
        tile[ty + j][tx] = (k < K && n < N) ? w[(size_t)k * N + n] : 0.f;
    }
    __syncthreads();
#pragma unroll
    for (int j = 0; j < 32; j += 8) {
        int n = n0 + ty + j, k = k0 + tx;
        if (n < N && k < K)
            Wh[(size_t)n * K + k] = __float2half(tile[tx][ty + j]);
    }
}

__global__ void k_prep(const float* __restrict__ x,
                       const float* __restrict__ w_in,  const float* __restrict__ w_off,
                       const float* __restrict__ w_mask, const float* __restrict__ w_out,
                       const float* __restrict__ c1_w,  const float* __restrict__ dn_w,
                       const float* __restrict__ b_off, const float* __restrict__ b_mask)
{
    __shared__ float tile[32][33];
    int id = blockIdx.x;
    if (id < 4096) {          // x transpose NCHW -> NHWC fp16
        int n  = id >> 10;
        int c0 = (id & 7) * 32;
        int p0 = ((id >> 3) & 127) * 32;
        int tx = threadIdx.x & 31, ty = threadIdx.x >> 5;
#pragma unroll
        for (int j = 0; j < 32; j += 8)
            tile[ty + j][tx] = x[(size_t)(n * CC + c0 + ty + j) * LPIX + p0 + tx];
        __syncthreads();
#pragma unroll
        for (int j = 0; j < 32; j += 8) {
            size_t o = (size_t)(n * LPIX + p0 + ty + j) * CC + c0 + tx;
            g_xsh[o] = __float2half(tile[tx][ty + j]);
        }
        return;
    }
    id -= 4096;
    if (id < 64)  { wprep_task(w_in,  g_winh, 256, 256, id & 7, id >> 3, tile); return; }
    id -= 64;
    if (id < 40)  { wprep_task(w_off, g_omh,  256, 144, id & 7, id >> 3, tile); return; }
    id -= 40;
    if (id < 24)  { wprep_task(w_mask, g_omh + 144 * 256, 256, 72, id & 7, id >> 3, tile); return; }
    id -= 24;
    if (id < 64)  { wprep_task(w_out, g_wouh, 256, 256, id & 7, id >> 3, tile); return; }
    id -= 64;
    if (id < 576) { wprep_task(c1_w,  g_c1h, 2304, 256, id % 72, id / 72, tile); return; }
    id -= 576;
    if (id < 576) { wprep_task(dn_w,  g_dnh, 2304, 256, id % 72, id / 72, tile); return; }
    id -= 576;
    if (id < 130) {
        int i = id * 256 + threadIdx.x;       // 4 batches * 260 border px * 32 float4
        if (i < 4 * 260 * 32) {
            int c4 = i & 31;
            int b  = (i >> 5) % 260;
            int n  = i / (260 * 32);
            int y, xx;
            if (b < 66)       { y = 0;       xx = b; }
            else if (b < 132) { y = 65;      xx = b - 66; }
            else if (b < 196) { y = b - 131; xx = 0; }
            else              { y = b - 195; xx = 65; }
            reinterpret_cast<float4*>(g_xp + ((size_t)(n * HP + y) * HP + xx) * CC)[c4] =
                make_float4(0.f, 0.f, 0.f, 0.f);
        }
        return;
    }
    int i = threadIdx.x;
    if (i < 144) g_bom[i] = b_off[i];
    else if (i < 216) g_bom[i] = b_mask[i - 144];
}

// ======================= depthwise + LN + GELU (4 px/block, fused reduce) ====
__global__ void k_dw(const float* __restrict__ dww, const float* __restrict__ dwb,
                     const float* __restrict__ lng, const float* __restrict__ lnb)
{
    int blk = blockIdx.x;                 // 4096 blocks
    int c   = threadIdx.x;
    int lane = c & 31, wid = c >> 5;
    int n  = blk >> 10;
    int h  = (blk >> 4) & 63;
    int w0 = (blk & 15) * 4;

    float v[3][6];
#pragma unroll
    for (int r = 0; r < 3; r++) {
        int y = h + r - 1;
#pragma unroll
        for (int j = 0; j < 6; j++) {
            int x = w0 + j - 1;
            v[r][j] = ((unsigned)y < 64u && (unsigned)x < 64u)
                ? __half2float(g_xsh[((size_t)((n * 64 + y) * 64 + x)) * 256 + c]) : 0.f;
        }
    }
    float wgt[9];
#pragma unroll
    for (int t = 0; t < 9; t++) wgt[t] = dww[t * 256 + c];
    float bias = dwb[c], gam = lng[c], bet = lnb[c];

    float acc[4], st[8];
#pragma unroll
    for (int p = 0; p < 4; p++) {
        float a = bias;
#pragma unroll
        for (int kh = 0; kh < 3; kh++)
#pragma unroll
            for (int kw = 0; kw < 3; kw++)
                a += v[kh][p + kw] * wgt[kh * 3 + kw];
        acc[p] = a;
        st[p] = a; st[4 + p] = a * a;
    }

    // fused reduction of 8 stats, 2 barriers total
    __shared__ float sh[8][8];
    __shared__ float res[8];
#pragma unroll
    for (int q = 0; q < 8; q++)
#pragma unroll
        for (int o = 16; o; o >>= 1)
            st[q] += __shfl_down_sync(0xffffffffu, st[q], o);
    if (lane == 0)
#pragma unroll
        for (int q = 0; q < 8; q++) sh[wid][q] = st[q];
    __syncthreads();
    if (wid == 0 && lane < 8) {
        float t = 0.f;
#pragma unroll
        for (int ww = 0; ww < 8; ww++) t += sh[ww][lane];
        res[lane] = t;
    }
    __syncthreads();

#pragma unroll
    for (int p = 0; p < 4; p++) {
        float mean = res[p] * (1.f / 256.f);
        float var  = res[4 + p] * (1.f / 256.f) - mean * mean;
        float rstd = rsqrtf(var + 1e-5f);
        float val = (acc[p] - mean) * rstd * gam + bet;
        val = 0.5f * val * (1.f + erff(val * 0.70710678118654752440f));
        g_th[((size_t)((n * 64 + h) * 64 + w0 + p)) * 256 + c] = __float2half(val);
    }
}

__global__ void k_sample()
{
    int pix  = blockIdx.x;
    int g    = threadIdx.x >> 5;
    int lane = threadIdx.x & 31;
    int n = pix >> 12, h = (pix >> 6) & 63, w = pix & 63;

    const float* ml = g_om + (size_t)pix * 216 + 144 + g * 9;
    float e[9], mx = -1e30f, s = 0.f;
#pragma unroll
    for (int p = 0; p < 9; p++) mx = fmaxf(mx, ml[p]);
#pragma unroll
    for (int p = 0; p < 9; p++) { e[p] = expf(ml[p] - mx); s += e[p]; }
    float inv = 1.f / s;

    const float2* off = reinterpret_cast<const float2*>(g_om + (size_t)pix * 216 + g * 18);
    const __half* img = g_xp + (size_t)n * HP * HP * CC + g * 32 + lane;
    float acc = 0.f;
#pragma unroll
    for (int p = 0; p < 9; p++) {
        float2 o2 = off[p];
        float px = (float)(w + p / 3) + o2.x;
        float py = (float)(h + p % 3) + o2.y;
        float wgt = e[p] * inv;
        float x0f = floorf(px), y0f = floorf(py);
        int x0 = (int)x0f, y0 = (int)y0f;
        float fx = px - x0f, fy = py - y0f;
#pragma unroll
        for (int dy = 0; dy < 2; dy++) {
            int yy = y0 + dy;
            if ((unsigned)yy >= (unsigned)HP) continue;
            float wy = dy ? fy : 1.f - fy;
#pragma unroll
            for (int dx = 0; dx < 2; dx++) {
                int xx = x0 + dx;
                if ((unsigned)xx >= (unsigned)HP) continue;
                float wx = dx ? fx : 1.f - fx;
                acc += __half2float(img[((size_t)yy * HP + xx) * CC]) * (wx * wy * wgt);
            }
        }
    }
    g_yh[(size_t)pix * 256 + g * 32 + lane] = __float2half(acc);
}

// GroupNorm(32) [+SiLU]; optional second input summed; values cached in smem
__global__ void k_gn(const float* __restrict__ in, const float* __restrict__ in2,
                     float* __restrict__ outf,
                     __half* __restrict__ oh,
                     const float* __restrict__ gamma, const float* __restrict__ beta,
                     int HWn, int do_silu, int out_nchw, int Wd)
{
    extern __shared__ float cache[];
    int n = blockIdx.x >> 5;
    int g = blockIdx.x & 31;
    int cnt = HWn * 8;
    const float* base  = in  + (size_t)n * HWn * 256 + g * 8;
    const float* base2 = in2 ? in2 + (size_t)n * HWn * 256 + g * 8 : nullptr;
    float s = 0.f, ss = 0.f;
    for (int i = threadIdx.x; i < cnt; i += 256) {
        size_t o = (size_t)(i >> 3) * 256 + (i & 7);
        float v = base[o];
        if (base2) v += base2[o];
        cache[i] = v;
        s += v; ss += v * v;
    }
    __shared__ float sh[32];
    block_reduce2(s, ss, sh);
    float mean = s / (float)cnt;
    float rstd = rsqrtf(ss / (float)cnt - mean * mean + 1e-5f);
    for (int i = threadIdx.x; i < cnt; i += 256) {
        int l = i >> 3, c = i & 7;
        float v = cache[i];
        v = (v - mean) * rstd * gamma[g * 8 + c] + beta[g * 8 + c];
        if (do_silu) v = v * (1.f / (1.f + expf(-v)));
        if (outf) {
            if (out_nchw)
                outf[(((size_t)n * 256 + g * 8 + c) * Wd + (l / Wd)) * Wd + (l % Wd)] = v;
            else
                outf[((size_t)n * HWn + l) * 256 + g * 8 + c] = v;
        }
        if (oh)
            oh[((size_t)n * HWn + l) * 256 + g * 8 + c] = __float2half(v);
    }
}

// ======================= mma.sync fp16 GEMM ==================================
#define MATB   16384
#define SM_TOT 196608

__global__ void __launch_bounds__(512, 1)
k_mma(const __half* __restrict__ Ah, const __half* __restrict__ Al,
      const __half* __restrict__ Bh,
      const float* __restrict__ bias, float* __restrict__ Cout, float* __restrict__ Cout2,
      __half* __restrict__ CoutH,
      int N, int Kloc, int Kfull, int mode, int owbits, int stride, int padout)
{
    extern __shared__ __align__(128) char smem[];
    const uint32_t sb = smem_u32(smem);
    const int tid = threadIdx.x;
    const int wid = tid >> 5, lane = tid & 31;
    const int g = lane >> 2, tg = lane & 3;
    const int warpM = wid & 3, warpN = wid >> 2;
    const int m0 = blockIdx.x * 128;
    const int n0 = blockIdx.y * 128;
    const int kb = blockIdx.z * Kloc;
    float* Cbase = (blockIdx.z == 0) ? Cout : Cout2;
    const float* bias_eff = (blockIdx.z == 0) ? bias : nullptr;
    const bool twoA  = (Al != nullptr);
    const int nmats  = twoA ? 3 : 2;
    const uint32_t stagesz = (uint32_t)nmats * MATB;
    const int S = Kloc >> 6;

    float acc[2][4][4];
#pragma unroll
    for (int i = 0; i < 2; i++)
#pragma unroll
        for (int j = 0; j < 4; j++)
#pragma unroll
            for (int r = 0; r < 4; r++) acc[i][j][r] = 0.f;

    auto fill = [&](int s, int st) {
        int gk = kb + (s << 6);
        int tap = gk >> 8, ci0 = gk & 255;
        int kh = tap / 3, kw = tap - 3 * kh;
        uint32_t stbase = sb + st * stagesz;
#pragma unroll 3
        for (int q = 0; q < 6; q++) {
            int cid = q * 512 + tid;           // 0..3071
            int mat = cid >> 10;
            if (mat >= nmats) break;
            int idx = cid & 1023;
            int r = idx >> 3, c = idx & 7;
            uint32_t dst = stbase + mat * MATB + r * 128 + ((c ^ (r & 7)) << 4);
            const __half* src;
            int sz = 16;
            if (mat != 1) {                     // A mats
                const __half* Ag = (mat == 0) ? Ah : Al;
                int m = m0 + r;
                if (mode == 0) {
                    src = Ag + (size_t)m * Kfull + gk + c * 8;
                } else {
                    int nn = m >> (2 * owbits);
                    int hw = m & ((1 << (2 * owbits)) - 1);
                    int ohh = hw >> owbits, oww = hw & ((1 << owbits) - 1);
                    int iy = ohh * stride + kh - 1, ix = oww * stride + kw - 1;
                    if ((unsigned)iy < 64u && (unsigned)ix < 64u)
                        src = Ag + ((size_t)((nn * 64 + iy) * 64 + ix)) * 256 + ci0 + c * 8;
                    else { src = Ag; sz = 0; }
                }
            } else {                            // B
                int n = n0 + r;
                if (n < N) src = Bh + (size_t)n * Kfull + gk + c * 8;
                else { src = Bh; sz = 0; }
            }
            CP_ASYNC16(dst, src, sz);
        }
    };

    const int lx = lane & 7;
    const uint32_t laneA_row = (uint32_t)(warpM * 32 + lx + ((lane >> 3) & 1) * 8) * 128;
    const uint32_t laneB_row = (uint32_t)(warpN * 32 + lx + ((lane >> 4) & 1) * 8) * 128;
    const int cselA = (lane >> 4) & 1;
    const int cselB = (lane >> 3) & 1;

    auto compute = [&](int st) {
        uint32_t bAh = sb + st * stagesz;
        uint32_t bBh = bAh + MATB;
        uint32_t bAl = bAh + 2 * MATB;
#pragma unroll
        for (int kk = 0; kk < 4; kk++) {
            uint32_t swzA = (uint32_t)(((kk * 2 + cselA) ^ lx) << 4);
            uint32_t swzB = (uint32_t)(((kk * 2 + cselB) ^ lx) << 4);
            uint32_t ah[2][4], al_[2][4], bh[4][2];
#pragma unroll
            for (int mi = 0; mi < 2; mi++) {
                LDSM4(ah[mi][0], ah[mi][1], ah[mi][2], ah[mi][3],
                      bAh + laneA_row + mi * 2048 + swzA);
                if (twoA)
                    LDSM4(al_[mi][0], al_[mi][1], al_[mi][2], al_[mi][3],
                          bAl + laneA_row + mi * 2048 + swzA);
            }
#pragma unroll
            for (int np = 0; np < 2; np++)
                LDSM4(bh[np*2][0], bh[np*2][1], bh[np*2+1][0], bh[np*2+1][1],
                      bBh + laneB_row + np * 2048 + swzB);
#pragma unroll
            for (int mi = 0; mi < 2; mi++)
#pragma unroll
                for (int ni = 0; ni < 4; ni++)
                    MMA_F16(acc[mi][ni], ah[mi], bh[ni]);
            if (twoA) {
#pragma unroll
                for (int mi = 0; mi < 2; mi++)
#pragma unroll
                    for (int ni = 0; ni < 4; ni++)
                        MMA_F16(acc[mi][ni], al_[mi], bh[ni]);
            }
        }
    };

    if (twoA) {
        for (int s = 0; s < 3; s++) { if (s < S) fill(s, s); CP_COMMIT(); }
        int st = 0;
        for (int s = 0; s < S; s++) {
            CP_WAIT(2);
            __syncthreads();
            int stf = st + 3; if (stf >= 4) stf -= 4;
            if (s + 3 < S) fill(s + 3, stf);
            CP_COMMIT();
            compute(st);
            if (++st == 4) st = 0;
        }
    } else {
        for (int s = 0; s < 4; s++) { if (s < S) fill(s, s); CP_COMMIT(); }
        int st = 0;
        for (int s = 0; s < S; s += 2) {
            CP_WAIT(2);
            __syncthreads();
            int f0 = st + 4; if (f0 >= 6) f0 -= 6;
            int f1 = st + 5; if (f1 >= 6) f1 -= 6;
            if (s + 4 < S) fill(s + 4, f0);
            CP_COMMIT();
            if (s + 5 < S) fill(s + 5, f1);
            CP_COMMIT();
            compute(st);
            int st1 = st + 1; if (st1 >= 6) st1 -= 6;
            compute(st1);
            st += 2; if (st >= 6) st -= 6;
        }
    }

    // ---- epilogue ----
#pragma unroll
    for (int mi = 0; mi < 2; mi++) {
        int mA = m0 + warpM * 32 + mi * 16 + g;
#pragma unroll
        for (int half = 0; half < 2; half++) {
            int m = mA + half * 8;
            if (padout) {
                int n = m >> 12, h = (m >> 6) & 63, w = m & 63;
                __half* orow = CoutH + ((size_t)(n * HP + h + 1) * HP + (w + 1)) * 256;
#pragma unroll
                for (int ni = 0; ni < 4; ni++) {
                    int nc = n0 + warpN * 32 + ni * 8 + tg * 2;
                    float v0 = acc[mi][ni][half * 2]     + bias[nc];
                    float v1 = acc[mi][ni][half * 2 + 1] + bias[nc + 1];
                    *reinterpret_cast<__half2*>(orow + nc) = __floats2half2_rn(v0, v1);
                }
            } else {
                float* orow = Cbase + (size_t)m * N;
#pragma unroll
                for (int ni = 0; ni < 4; ni++) {
                    int nc = n0 + warpN * 32 + ni * 8 + tg * 2;
                    float b0 = bias_eff ? bias_eff[nc < N ? nc : 0] : 0.f;
                    float b1 = bias_eff ? bias_eff[nc + 1 < N ? nc + 1 : 0] : 0.f;
                    if (nc < N)     orow[nc]     = acc[mi][ni][half * 2]     + b0;
                    if (nc + 1 < N) orow[nc + 1] = acc[mi][ni][half * 2 + 1] + b1;
                }
            }
        }
    }
}

// ======================= launch =============================================
extern "C" void kernel_launch(void* const* d_in, const int* in_sizes, int n_in,
                              void* d_out, int out_size)
{
    const float* x      = (const float*)d_in[0];
    const float* w_in   = (const float*)d_in[1];
    const float* b_in   = (const float*)d_in[2];
    const float* dw_w   = (const float*)d_in[3];
    const float* dw_b   = (const float*)d_in[4];
    const float* ln_g   = (const float*)d_in[5];
    const float* ln_b   = (const float*)d_in[6];
    const float* w_off  = (const float*)d_in[7];
    const float* b_off  = (const float*)d_in[8];
    const float* w_mask = (const float*)d_in[9];
    const float* b_mask = (const float*)d_in[10];
    const float* w_out  = (const float*)d_in[11];
    const float* b_out  = (const float*)d_in[12];
    const float* gn1_g  = (const float*)d_in[13];
    const float* gn1_b  = (const float*)d_in[14];
    const float* c1_w   = (const float*)d_in[15];
    const float* c1_b   = (const float*)d_in[16];
    const float* gn2_g  = (const float*)d_in[17];
    const float* gn2_b  = (const float*)d_in[18];
    const float* dn_w   = (const float*)d_in[19];
    const float* dn_b   = (const float*)d_in[20];
    const float* gn3_g  = (const float*)d_in[21];
    const float* gn3_b  = (const float*)d_in[22];

    cudaFuncSetAttribute(k_mma, cudaFuncAttributeMaxDynamicSharedMemorySize, SM_TOT);
    cudaFuncSetAttribute(k_gn,  cudaFuncAttributeMaxDynamicSharedMemorySize, 131072);

    float *om, *bom, *y2, *dn;
    __half *xp, *xsh, *th, *yh, *gh;
    __half *winh, *omh, *wouh, *c1h, *dnh;
    cudaGetSymbolAddress((void**)&xp,  g_xp);
    cudaGetSymbolAddress((void**)&om,  g_om);
    cudaGetSymbolAddress((void**)&bom, g_bom);
    cudaGetSymbolAddress((void**)&y2,  g_y2);
    cudaGetSymbolAddress((void**)&dn,  g_dn);
    cudaGetSymbolAddress((void**)&xsh, g_xsh);
    cudaGetSymbolAddress((void**)&th,  g_th);
    cudaGetSymbolAddress((void**)&yh,  g_yh);
    cudaGetSymbolAddress((void**)&gh,  g_gh);
    cudaGetSymbolAddress((void**)&winh, g_winh);
    cudaGetSymbolAddress((void**)&omh,  g_omh);
    cudaGetSymbolAddress((void**)&wouh, g_wouh);
    cudaGetSymbolAddress((void**)&c1h,  g_c1h);  cudaGetSymbolAddress((void**)&dnh,  g_dnh);

    // 0: transpose + all weight preps + border zero + bias (single launch)
    k_prep<<<5571, 256>>>(x, w_in, w_off, w_mask, w_out, c1_w, dn_w, b_off, b_mask);
    // 1: input projection -> padded xp fp16 (1-term)
    k_mma<<<dim3(128, 2, 1), 512, SM_TOT>>>(xsh, nullptr, winh, b_in, nullptr, nullptr, xp,
                                            256, 256, 256, 0, 0, 0, 1);
    // 2: depthwise + LN + GELU -> t (fp16), 4 px/block, fused reduction
    k_dw<<<4096, 256>>>(dw_w, dw_b, ln_g, ln_b);
    // 3: fused offset+mask projection (N=216, 1-term)
    k_mma<<<dim3(128, 2, 1), 512, SM_TOT>>>(th, nullptr, omh, bom, om, nullptr, nullptr,
                                            216, 256, 256, 0, 0, 0, 0);
    // 4: deformable sampling -> y (fp16)
    k_sample<<<NPIX, 256>>>();
    // 5: output projection -> y2 (1-term)
    k_mma<<<dim3(128, 2, 1), 512, SM_TOT>>>(yh, nullptr, wouh, b_out, y2, nullptr, nullptr,
                                            256, 256, 256, 0, 0, 0, 0);
    // 6: GN1 + SiLU -> fp16 (smem-cached)
    k_gn<<<128, 256, 131072>>>(y2, nullptr, (float*)nullptr, gh, gn1_g, gn1_b, 4096, 1, 0, 64);
    // 7: conv1 3x3 implicit im2col (K=2304, 1-term, paired stages) -> y2
    k_mma<<<dim3(128, 2, 1), 512, SM_TOT>>>(gh, nullptr, c1h, c1_b, y2, nullptr, nullptr,
                                            256, 2304, 2304, 1, 6, 1, 0);
    // 8: GN2 + SiLU -> fp16 (smem-cached)
    k_gn<<<128, 256, 131072>>>(y2, nullptr, (float*)nullptr, gh, gn2_g, gn2_b, 4096, 1, 0, 64);
    // 9: down conv 3x3 stride2 (1-term, K-split z=2: dn + partial in y2)
    k_mma<<<dim3(32, 2, 2), 512, SM_TOT>>>(gh, nullptr, dnh, dn_b, dn, y2, nullptr,
                                           256, 1152, 2304, 1, 5, 2, 0);
    // 10: GN3 (sums dn + y2 partial, smem-cached) -> NCHW output
    k_gn<<<128, 256, 32768>>>(dn, y2, (float*)d_out, (__half*)nullptr,
                              gn3_g, gn3_b, 1024, 0, 1, 32);
}

// round 17
// speedup vs baseline: 1.4277x; 1.1481x over previous
#include <cuda_runtime.h>
#include <cuda_fp16.h>
#include <cstdint>
#include <math.h>

#define NB   4
#define CC   256
#define HP   66
#define LPIX 4096
#define NPIX 16384

// ======================= PTX helpers ========================================
__device__ __forceinline__ uint32_t smem_u32(const void* p) {
    uint32_t a;
    asm("{ .reg .u64 t; cvta.to.shared.u64 t, %1; cvt.u32.u64 %0, t; }" : "=r"(a) : "l"(p));
    return a;
}
#define CP_ASYNC16(dst, src, sz) \
    asm volatile("cp.async.cg.shared.global [%0], [%1], 16, %2;" \
                 :: "r"(dst), "l"(src), "r"(sz) : "memory")
#define CP_COMMIT() asm volatile("cp.async.commit_group;" ::: "memory")
#define CP_WAIT(n)  asm volatile("cp.async.wait_group %0;" :: "n"(n) : "memory")

#define LDSM4(r0, r1, r2, r3, a) \
    asm volatile("ldmatrix.sync.aligned.m8n8.x4.shared.b16 {%0,%1,%2,%3}, [%4];" \
        : "=r"(r0), "=r"(r1), "=r"(r2), "=r"(r3) : "r"(a))

#define MMA_F16(acc, A, B) \
    asm volatile("mma.sync.aligned.m16n8k16.row.col.f32.f16.f16.f32 " \
        "{%0,%1,%2,%3}, {%4,%5,%6,%7}, {%8,%9}, {%0,%1,%2,%3};" \
        : "+f"((acc)[0]), "+f"((acc)[1]), "+f"((acc)[2]), "+f"((acc)[3]) \
        : "r"((A)[0]), "r"((A)[1]), "r"((A)[2]), "r"((A)[3]), \
          "r"((B)[0]), "r"((B)[1]))

// ======================= scratch ============================================
__device__ __half g_xsh[NPIX * CC];
__device__ __half g_xp [NB * HP * HP * CC];          // padded x_proj, fp16
__device__ __half g_th [NPIX * CC];
__device__ float  g_om [NPIX * 216];
__device__ float  g_bom[216];
__device__ __half g_yh [NPIX * CC];
__device__ float  g_y2 [NPIX * CC];
__device__ __half g_gh [NPIX * CC];
__device__ float  g_dn [NB * 32 * 32 * CC];
// weights: [N, K] fp16 (hi only)
__device__ __half g_winh[256*256];
__device__ __half g_omh [216*256];
__device__ __half g_wouh[256*256];
__device__ __half g_c1h [256*2304];
__device__ __half g_dnh [256*2304];

// ======================= misc ===============================================
__device__ __forceinline__ void block_reduce2(float &a, float &b, float* sh) {
    int lane = threadIdx.x & 31, wid = threadIdx.x >> 5;
#pragma unroll
    for (int o = 16; o; o >>= 1) {
        a += __shfl_down_sync(0xffffffffu, a, o);
        b += __shfl_down_sync(0xffffffffu, b, o);
    }
    if (lane == 0) { sh[wid] = a; sh[8 + wid] = b; }
    __syncthreads();
    if (wid == 0) {
        a = (lane < 8) ? sh[lane] : 0.f;
        b = (lane < 8) ? sh[8 + lane] : 0.f;
#pragma unroll
        for (int o = 4; o; o >>= 1) {
            a += __shfl_down_sync(0xffffffffu, a, o);
            b += __shfl_down_sync(0xffffffffu, b, o);
        }
        if (lane == 0) { sh[16] = a; sh[17] = b; }
    }
    __syncthreads();
    a = sh[16]; b = sh[17];
}

// ======================= mega-prep: transpose + weight preps + border + bias =
__device__ __forceinline__ void wprep_task(const float* __restrict__ w,
                                           __half* __restrict__ Wh,
                                           int K, int N, int bx, int by,
                                           float (*tile)[33]) {
    int tx = threadIdx.x & 31, ty = threadIdx.x >> 5;   // 32 x 8
    int k0 = bx * 32, n0 = by * 32;
#pragma unroll
    for (int j = 0; j < 32; j += 8) {
        int k = k0 + ty + j, n = n0 + tx;
        tile[ty + j][tx] = (k < K && n < N) ? w[(size_t)k * N + n] : 0.f;
    }
    __syncthreads();
#pragma unroll
    for (int j = 0; j < 32; j += 8) {
        int n = n0 + ty + j, k = k0 + tx;
        if (n < N && k < K)
            Wh[(size_t)n * K + k] = __float2half(tile[tx][ty + j]);
    }
}

__global__ void k_prep(const float* __restrict__ x,
                       const float* __restrict__ w_in,  const float* __restrict__ w_off,
                       const float* __restrict__ w_mask, const float* __restrict__ w_out,
                       const float* __restrict__ c1_w,  const float* __restrict__ dn_w,
                       const float* __restrict__ b_off, const float* __restrict__ b_mask)
{
    __shared__ float tile[32][33];
    int id = blockIdx.x;
    if (id < 4096) {          // x transpose NCHW -> NHWC fp16
        int n  = id >> 10;
        int c0 = (id & 7) * 32;
        int p0 = ((id >> 3) & 127) * 32;
        int tx = threadIdx.x & 31, ty = threadIdx.x >> 5;
#pragma unroll
        for (int j = 0; j < 32; j += 8)
            tile[ty + j][tx] = x[(size_t)(n * CC + c0 + ty + j) * LPIX + p0 + tx];
        __syncthreads();
#pragma unroll
        for (int j = 0; j < 32; j += 8) {
            size_t o = (size_t)(n * LPIX + p0 + ty + j) * CC + c0 + tx;
            g_xsh[o] = __float2half(tile[tx][ty + j]);
        }
        return;
    }
    id -= 4096;
    if (id < 64)  { wprep_task(w_in,  g_winh, 256, 256, id & 7, id >> 3, tile); return; }
    id -= 64;
    if (id < 40)  { wprep_task(w_off, g_omh,  256, 144, id & 7, id >> 3, tile); return; }
    id -= 40;
    if (id < 24)  { wprep_task(w_mask, g_omh + 144 * 256, 256, 72, id & 7, id >> 3, tile); return; }
    id -= 24;
    if (id < 64)  { wprep_task(w_out, g_wouh, 256, 256, id & 7, id >> 3, tile); return; }
    id -= 64;
    if (id < 576) { wprep_task(c1_w,  g_c1h, 2304, 256, id % 72, id / 72, tile); return; }
    id -= 576;
    if (id < 576) { wprep_task(dn_w,  g_dnh, 2304, 256, id % 72, id / 72, tile); return; }
    id -= 576;
    if (id < 130) {
        int i = id * 256 + threadIdx.x;       // 4 batches * 260 border px * 32 float4
        if (i < 4 * 260 * 32) {
            int c4 = i & 31;
            int b  = (i >> 5) % 260;
            int n  = i / (260 * 32);
            int y, xx;
            if (b < 66)       { y = 0;       xx = b; }
            else if (b < 132) { y = 65;      xx = b - 66; }
            else if (b < 196) { y = b - 131; xx = 0; }
            else              { y = b - 195; xx = 65; }
            reinterpret_cast<float4*>(g_xp + ((size_t)(n * HP + y) * HP + xx) * CC)[c4] =
                make_float4(0.f, 0.f, 0.f, 0.f);
        }
        return;
    }
    int i = threadIdx.x;
    if (i < 144) g_bom[i] = b_off[i];
    else if (i < 216) g_bom[i] = b_mask[i - 144];
}

// ======================= depthwise + LN + GELU (4 px/block, fused reduce) ====
__global__ void k_dw(const float* __restrict__ dww, const float* __restrict__ dwb,
                     const float* __restrict__ lng, const float* __restrict__ lnb)
{
    int blk = blockIdx.x;                 // 4096 blocks
    int c   = threadIdx.x;
    int lane = c & 31, wid = c >> 5;
    int n  = blk >> 10;
    int h  = (blk >> 4) & 63;
    int w0 = (blk & 15) * 4;

    float v[3][6];
#pragma unroll
    for (int r = 0; r < 3; r++) {
        int y = h + r - 1;
#pragma unroll
        for (int j = 0; j < 6; j++) {
            int x = w0 + j - 1;
            v[r][j] = ((unsigned)y < 64u && (unsigned)x < 64u)
                ? __half2float(g_xsh[((size_t)((n * 64 + y) * 64 + x)) * 256 + c]) : 0.f;
        }
    }
    float wgt[9];
#pragma unroll
    for (int t = 0; t < 9; t++) wgt[t] = dww[t * 256 + c];
    float bias = dwb[c], gam = lng[c], bet = lnb[c];

    float acc[4], st[8];
#pragma unroll
    for (int p = 0; p < 4; p++) {
        float a = bias;
#pragma unroll
        for (int kh = 0; kh < 3; kh++)
#pragma unroll
            for (int kw = 0; kw < 3; kw++)
                a += v[kh][p + kw] * wgt[kh * 3 + kw];
        acc[p] = a;
        st[p] = a; st[4 + p] = a * a;
    }

    __shared__ float sh[8][8];
    __shared__ float res[8];
#pragma unroll
    for (int q = 0; q < 8; q++)
#pragma unroll
        for (int o = 16; o; o >>= 1)
            st[q] += __shfl_down_sync(0xffffffffu, st[q], o);
    if (lane == 0)
#pragma unroll
        for (int q = 0; q < 8; q++) sh[wid][q] = st[q];
    __syncthreads();
    if (wid == 0 && lane < 8) {
        float t = 0.f;
#pragma unroll
        for (int ww = 0; ww < 8; ww++) t += sh[ww][lane];
        res[lane] = t;
    }
    __syncthreads();

#pragma unroll
    for (int p = 0; p < 4; p++) {
        float mean = res[p] * (1.f / 256.f);
        float var  = res[4 + p] * (1.f / 256.f) - mean * mean;
        float rstd = rsqrtf(var + 1e-5f);
        float val = (acc[p] - mean) * rstd * gam + bet;
        val = 0.5f * val * (1.f + erff(val * 0.70710678118654752440f));
        g_th[((size_t)((n * 64 + h) * 64 + w0 + p)) * 256 + c] = __float2half(val);
    }
}

// ======================= deformable sampling (2 px/warp, half2 lanes) ========
__global__ void k_sample()
{
    int blk  = blockIdx.x;                // 8192 blocks
    int g    = threadIdx.x >> 5;
    int lane = threadIdx.x & 31;
    int pix  = blk * 2 + (lane >> 4);
    int ch   = (lane & 15) * 2;
    int n = pix >> 12, h = (pix >> 6) & 63, w = pix & 63;

    const float* ml = g_om + (size_t)pix * 216 + 144 + g * 9;
    float e[9], mx = -1e30f, s = 0.f;
#pragma unroll
    for (int p = 0; p < 9; p++) mx = fmaxf(mx, ml[p]);
#pragma unroll
    for (int p = 0; p < 9; p++) { e[p] = expf(ml[p] - mx); s += e[p]; }
    float inv = 1.f / s;

    const float2* off = reinterpret_cast<const float2*>(g_om + (size_t)pix * 216 + g * 18);
    const __half* imgp = g_xp + (size_t)n * HP * HP * CC + g * 32 + ch;
    float acc0 = 0.f, acc1 = 0.f;
#pragma unroll
    for (int p = 0; p < 9; p++) {
        float2 o2 = off[p];
        float px = (float)(w + p / 3) + o2.x;
        float py = (float)(h + p % 3) + o2.y;
        float wgt = e[p] * inv;
        float x0f = floorf(px), y0f = floorf(py);
        int x0 = (int)x0f, y0 = (int)y0f;
        float fx = px - x0f, fy = py - y0f;
#pragma unroll
        for (int dy = 0; dy < 2; dy++) {
            int yy = y0 + dy;
            if ((unsigned)yy >= (unsigned)HP) continue;
            float wy = dy ? fy : 1.f - fy;
#pragma unroll
            for (int dx = 0; dx < 2; dx++) {
                int xx = x0 + dx;
                if ((unsigned)xx >= (unsigned)HP) continue;
                float wx = dx ? fx : 1.f - fx;
                float cw = wx * wy * wgt;
                __half2 hv = *reinterpret_cast<const __half2*>(
                                 imgp + ((size_t)yy * HP + xx) * CC);
                float2 f = __half22float2(hv);
                acc0 += f.x * cw;
                acc1 += f.y * cw;
            }
        }
    }
    *reinterpret_cast<__half2*>(g_yh + (size_t)pix * 256 + g * 32 + ch) =
        __floats2half2_rn(acc0, acc1);
}

// GroupNorm(32) [+SiLU]; input fp16 (inh) OR fp32 (+optional second summed)
__global__ void k_gn(const float* __restrict__ in, const float* __restrict__ in2,
                     const __half* __restrict__ inh,
                     float* __restrict__ outf,
                     __half* __restrict__ oh,
                     const float* __restrict__ gamma, const float* __restrict__ beta,
                     int HWn, int do_silu, int out_nchw, int Wd)
{
    extern __shared__ float cache[];
    int n = blockIdx.x >> 5;
    int g = blockIdx.x & 31;
    int cnt = HWn * 8;
    size_t gbase = (size_t)n * HWn * 256 + g * 8;
    float s = 0.f, ss = 0.f;
    for (int i = threadIdx.x; i < cnt; i += 256) {
        size_t o = gbase + (size_t)(i >> 3) * 256 + (i & 7);
        float v;
        if (inh) v = __half2float(inh[o]);
        else { v = in[o]; if (in2) v += in2[o]; }
        cache[i] = v;
        s += v; ss += v * v;
    }
    __shared__ float sh[32];
    block_reduce2(s, ss, sh);
    float mean = s / (float)cnt;
    float rstd = rsqrtf(ss / (float)cnt - mean * mean + 1e-5f);
    for (int i = threadIdx.x; i < cnt; i += 256) {
        int l = i >> 3, c = i & 7;
        float v = cache[i];
        v = (v - mean) * rstd * gamma[g * 8 + c] + beta[g * 8 + c];
        if (do_silu) v = v * (1.f / (1.f + expf(-v)));
        if (outf) {
            if (out_nchw)
                outf[(((size_t)n * 256 + g * 8 + c) * Wd + (l / Wd)) * Wd + (l % Wd)] = v;
            else
                outf[((size_t)n * HWn + l) * 256 + g * 8 + c] = v;
        }
        if (oh)
            oh[((size_t)n * HWn + l) * 256 + g * 8 + c] = __float2half(v);
    }
}

// ======================= mma.sync fp16 GEMM ==================================
// padout: 0 = fp32 plain (Cout/Cout2 by z), 1 = fp16 padded 66x66 (CoutH),
//         2 = fp16 plain (CoutH)
#define MATB   16384
#define SM_TOT 196608

__global__ void __launch_bounds__(512, 1)
k_mma(const __half* __restrict__ Ah, const __half* __restrict__ Al,
      const __half* __restrict__ Bh,
      const float* __restrict__ bias, float* __restrict__ Cout, float* __restrict__ Cout2,
      __half* __restrict__ CoutH,
      int N, int Kloc, int Kfull, int mode, int owbits, int stride, int padout)
{
    extern __shared__ __align__(128) char smem[];
    const uint32_t sb = smem_u32(smem);
    const int tid = threadIdx.x;
    const int wid = tid >> 5, lane = tid & 31;
    const int g = lane >> 2, tg = lane & 3;
    const int warpM = wid & 3, warpN = wid >> 2;
    const int m0 = blockIdx.x * 128;
    const int n0 = blockIdx.y * 128;
    const int kb = blockIdx.z * Kloc;
    float* Cbase = (blockIdx.z == 0) ? Cout : Cout2;
    const float* bias_eff = (blockIdx.z == 0) ? bias : nullptr;
    const bool twoA  = (Al != nullptr);
    const int nmats  = twoA ? 3 : 2;
    const uint32_t stagesz = (uint32_t)nmats * MATB;
    const int S = Kloc >> 6;

    float acc[2][4][4];
#pragma unroll
    for (int i = 0; i < 2; i++)
#pragma unroll
        for (int j = 0; j < 4; j++)
#pragma unroll
            for (int r = 0; r < 4; r++) acc[i][j][r] = 0.f;

    auto fill = [&](int s, int st) {
        int gk = kb + (s << 6);
        int tap = gk >> 8, ci0 = gk & 255;
        int kh = tap / 3, kw = tap - 3 * kh;
        uint32_t stbase = sb + st * stagesz;
#pragma unroll 3
        for (int q = 0; q < 6; q++) {
            int cid = q * 512 + tid;           // 0..3071
            int mat = cid >> 10;
            if (mat >= nmats) break;
            int idx = cid & 1023;
            int r = idx >> 3, c = idx & 7;
            uint32_t dst = stbase + mat * MATB + r * 128 + ((c ^ (r & 7)) << 4);
            const __half* src;
            int sz = 16;
            if (mat != 1) {                     // A mats
                const __half* Ag = (mat == 0) ? Ah : Al;
                int m = m0 + r;
                if (mode == 0) {
                    src = Ag + (size_t)m * Kfull + gk + c * 8;
                } else {
                    int nn = m >> (2 * owbits);
                    int hw = m & ((1 << (2 * owbits)) - 1);
                    int ohh = hw >> owbits, oww = hw & ((1 << owbits) - 1);
                    int iy = ohh * stride + kh - 1, ix = oww * stride + kw - 1;
                    if ((unsigned)iy < 64u && (unsigned)ix < 64u)
                        src = Ag + ((size_t)((nn * 64 + iy) * 64 + ix)) * 256 + ci0 + c * 8;
                    else { src = Ag; sz = 0; }
                }
            } else {                            // B
                int n = n0 + r;
                if (n < N) src = Bh + (size_t)n * Kfull + gk + c * 8;
                else { src = Bh; sz = 0; }
            }
            CP_ASYNC16(dst, src, sz);
        }
    };

    const int lx = lane & 7;
    const uint32_t laneA_row = (uint32_t)(warpM * 32 + lx + ((lane >> 3) & 1) * 8) * 128;
    const uint32_t laneB_row = (uint32_t)(warpN * 32 + lx + ((lane >> 4) & 1) * 8) * 128;
    const int cselA = (lane >> 4) & 1;
    const int cselB = (lane >> 3) & 1;

    auto compute = [&](int st) {
        uint32_t bAh = sb + st * stagesz;
        uint32_t bBh = bAh + MATB;
        uint32_t bAl = bAh + 2 * MATB;
#pragma unroll
        for (int kk = 0; kk < 4; kk++) {
            uint32_t swzA = (uint32_t)(((kk * 2 + cselA) ^ lx) << 4);
            uint32_t swzB = (uint32_t)(((kk * 2 + cselB) ^ lx) << 4);
            uint32_t ah[2][4], al_[2][4], bh[4][2];
#pragma unroll
            for (int mi = 0; mi < 2; mi++) {
                LDSM4(ah[mi][0], ah[mi][1], ah[mi][2], ah[mi][3],
                      bAh + laneA_row + mi * 2048 + swzA);
                if (twoA)
                    LDSM4(al_[mi][0], al_[mi][1], al_[mi][2], al_[mi][3],
                          bAl + laneA_row + mi * 2048 + swzA);
            }
#pragma unroll
            for (int np = 0; np < 2; np++)
                LDSM4(bh[np*2][0], bh[np*2][1], bh[np*2+1][0], bh[np*2+1][1],
                      bBh + laneB_row + np * 2048 + swzB);
#pragma unroll
            for (int mi = 0; mi < 2; mi++)
#pragma unroll
                for (int ni = 0; ni < 4; ni++)
                    MMA_F16(acc[mi][ni], ah[mi], bh[ni]);
            if (twoA) {
#pragma unroll
                for (int mi = 0; mi < 2; mi++)
#pragma unroll
                    for (int ni = 0; ni < 4; ni++)
                        MMA_F16(acc[mi][ni], al_[mi], bh[ni]);
            }
        }
    };

    if (twoA) {
        for (int s = 0; s < 3; s++) { if (s < S) fill(s, s); CP_COMMIT(); }
        int st = 0;
        for (int s = 0; s < S; s++) {
            CP_WAIT(2);
            __syncthreads();
            int stf = st + 3; if (stf >= 4) stf -= 4;
            if (s + 3 < S) fill(s + 3, stf);
            CP_COMMIT();
            compute(st);
            if (++st == 4) st = 0;
        }
    } else {
        for (int s = 0; s < 4; s++) { if (s < S) fill(s, s); CP_COMMIT(); }
        int st = 0;
        for (int s = 0; s < S; s += 2) {
            CP_WAIT(2);
            __syncthreads();
            int f0 = st + 4; if (f0 >= 6) f0 -= 6;
            int f1 = st + 5; if (f1 >= 6) f1 -= 6;
            if (s + 4 < S) fill(s + 4, f0);
            CP_COMMIT();
            if (s + 5 < S) fill(s + 5, f1);
            CP_COMMIT();
            compute(st);
            int st1 = st + 1; if (st1 >= 6) st1 -= 6;
            compute(st1);
            st += 2; if (st >= 6) st -= 6;
        }
    }

    // ---- epilogue ----
#pragma unroll
    for (int mi = 0; mi < 2; mi++) {
        int mA = m0 + warpM * 32 + mi * 16 + g;
#pragma unroll
        for (int half = 0; half < 2; half++) {
            int m = mA + half * 8;
            if (padout == 1) {
                int n = m >> 12, h = (m >> 6) & 63, w = m & 63;
                __half* orow = CoutH + ((size_t)(n * HP + h + 1) * HP + (w + 1)) * 256;
#pragma unroll
                for (int ni = 0; ni < 4; ni++) {
                    int nc = n0 + warpN * 32 + ni * 8 + tg * 2;
                    float v0 = acc[mi][ni][half * 2]     + bias[nc];
                    float v1 = acc[mi][ni][half * 2 + 1] + bias[nc + 1];
                    *reinterpret_cast<__half2*>(orow + nc) = __floats2half2_rn(v0, v1);
                }
            } else if (padout == 2) {
                __half* orow = CoutH + (size_t)m * N;
#pragma unroll
                for (int ni = 0; ni < 4; ni++) {
                    int nc = n0 + warpN * 32 + ni * 8 + tg * 2;
                    float v0 = acc[mi][ni][half * 2]     + bias[nc];
                    float v1 = acc[mi][ni][half * 2 + 1] + bias[nc + 1];
                    *reinterpret_cast<__half2*>(orow + nc) = __floats2half2_rn(v0, v1);
                }
            } else {
                float* orow = Cbase + (size_t)m * N;
#pragma unroll
                for (int ni = 0; ni < 4; ni++) {
                    int nc = n0 + warpN * 32 + ni * 8 + tg * 2;
                    float b0 = bias_eff ? bias_eff[nc < N ? nc : 0] : 0.f;
                    float b1 = bias_eff ? bias_eff[nc + 1 < N ? nc + 1 : 0] : 0.f;
                    if (nc < N)     orow[nc]     = acc[mi][ni][half * 2]     + b0;
                    if (nc + 1 < N) orow[nc + 1] = acc[mi][ni][half * 2 + 1] + b1;
                }
            }
        }
    }
}

// ======================= launch =============================================
extern "C" void kernel_launch(void* const* d_in, const int* in_sizes, int n_in,
                              void* d_out, int out_size)
{
    const float* x      = (const float*)d_in[0];
    const float* w_in   = (const float*)d_in[1];
    const float* b_in   = (const float*)d_in[2];
    const float* dw_w   = (const float*)d_in[3];
    const float* dw_b   = (const float*)d_in[4];
    const float* ln_g   = (const float*)d_in[5];
    const float* ln_b   = (const float*)d_in[6];
    const float* w_off  = (const float*)d_in[7];
    const float* b_off  = (const float*)d_in[8];
    const float* w_mask = (const float*)d_in[9];
    const float* b_mask = (const float*)d_in[10];
    const float* w_out  = (const float*)d_in[11];
    const float* b_out  = (const float*)d_in[12];
    const float* gn1_g  = (const float*)d_in[13];
    const float* gn1_b  = (const float*)d_in[14];
    const float* c1_w   = (const float*)d_in[15];
    const float* c1_b   = (const float*)d_in[16];
    const float* gn2_g  = (const float*)d_in[17];
    const float* gn2_b  = (const float*)d_in[18];
    const float* dn_w   = (const float*)d_in[19];
    const float* dn_b   = (const float*)d_in[20];
    const float* gn3_g  = (const float*)d_in[21];
    const float* gn3_b  = (const float*)d_in[22];

    cudaFuncSetAttribute(k_mma, cudaFuncAttributeMaxDynamicSharedMemorySize, SM_TOT);
    cudaFuncSetAttribute(k_gn,  cudaFuncAttributeMaxDynamicSharedMemorySize, 131072);

    float *om, *bom, *y2, *dn;
    __half *xp, *xsh, *th, *yh, *gh;
    __half *winh, *omh, *wouh, *c1h, *dnh;
    cudaGetSymbolAddress((void**)&xp,  g_xp);
    cudaGetSymbolAddress((void**)&om,  g_om);
    cudaGetSymbolAddress((void**)&bom, g_bom);
    cudaGetSymbolAddress((void**)&y2,  g_y2);
    cudaGetSymbolAddress((void**)&dn,  g_dn);
    cudaGetSymbolAddress((void**)&xsh, g_xsh);
    cudaGetSymbolAddress((void**)&th,  g_th);
    cudaGetSymbolAddress((void**)&yh,  g_yh);
    cudaGetSymbolAddress((void**)&gh,  g_gh);
    cudaGetSymbolAddress((void**)&winh, g_winh);
    cudaGetSymbolAddress((void**)&omh,  g_omh);
    cudaGetSymbolAddress((void**)&wouh, g_wouh);
    cudaGetSymbolAddress((void**)&c1h,  g_c1h);  cudaGetSymbolAddress((void**)&dnh,  g_dnh);

    // 0: transpose + all weight preps + border zero + bias (single launch)
    k_prep<<<5571, 256>>>(x, w_in, w_off, w_mask, w_out, c1_w, dn_w, b_off, b_mask);
    // 1: input projection -> padded xp fp16 (1-term)
    k_mma<<<dim3(128, 2, 1), 512, SM_TOT>>>(xsh, nullptr, winh, b_in, nullptr, nullptr, xp,
                                            256, 256, 256, 0, 0, 0, 1);
    // 2: depthwise + LN + GELU -> th (fp16)
    k_dw<<<4096, 256>>>(dw_w, dw_b, ln_g, ln_b);
    // 3: fused offset+mask projection (N=216, 1-term)
    k_mma<<<dim3(128, 2, 1), 512, SM_TOT>>>(th, nullptr, omh, bom, om, nullptr, nullptr,
                                            216, 256, 256, 0, 0, 0, 0);
    // 4: deformable sampling -> yh (2 px/warp, half2)
    k_sample<<<8192, 256>>>();
    // 5: output projection -> th fp16 (plain)
    k_mma<<<dim3(128, 2, 1), 512, SM_TOT>>>(yh, nullptr, wouh, b_out, nullptr, nullptr, th,
                                            256, 256, 256, 0, 0, 0, 2);
    // 6: GN1 + SiLU (fp16 in) -> gh
    k_gn<<<128, 256, 131072>>>(nullptr, nullptr, th, (float*)nullptr, gh,
                               gn1_g, gn1_b, 4096, 1, 0, 64);
    // 7: conv1 3x3 implicit im2col (1-term) -> yh fp16 (plain)
    k_mma<<<dim3(128, 2, 1), 512, SM_TOT>>>(gh, nullptr, c1h, c1_b, nullptr, nullptr, yh,
                                            256, 2304, 2304, 1, 6, 1, 2);
    // 8: GN2 + SiLU (fp16 in) -> gh
    k_gn<<<128, 256, 131072>>>(nullptr, nullptr, yh, (float*)nullptr, gh,
                               gn2_g, gn2_b, 4096, 1, 0, 64);
    // 9: down conv 3x3 stride2 (1-term, K-split z=2: dn + partial in y2, fp32)
    k_mma<<<dim3(32, 2, 2), 512, SM_TOT>>>(gh, nullptr, dnh, dn_b, dn, y2, nullptr,
                                           256, 1152, 2304, 1, 5, 2, 0);
    // 10: GN3 (fp32 dn + y2 partial) -> NCHW output
    k_gn<<<128, 256, 32768>>>(dn, y2, (const __half*)nullptr, (float*)d_out, (__half*)nullptr,
                              gn3_g, gn3_b, 1024, 0, 1, 32);
}